// round 1
// baseline (speedup 1.0000x reference)
#include <cuda_runtime.h>
#include <cuda_bf16.h>
#include <math.h>

// ---------------- problem constants ----------------
#define BB 2
#define TT 2048
#define CC 512
#define HH 8
#define DP 32
#define DH 64
#define MM (BB*TT)          // 4096 rows

// ---------------- scratch (no allocs allowed) ----------------
__device__ float g_wqk[512*512];     // repacked [n][d]; n<256 -> q (h=n/32,o=n%32), n>=256 -> k
__device__ float g_qk [MM*512];      // X @ Wqk^T   [bt][n]
__device__ float g_q  [BB*HH*TT*DP]; // [b,h,t,o] after rope*gain
__device__ float g_k  [BB*HH*TT*DP];
__device__ float g_v  [MM*CC];       // [bt][c], c = h*64+d
__device__ float g_y  [MM*CC];
__device__ float g_h  [MM*CC];
__device__ float g_t0 [MM*CC];
__device__ float g_ln [MM*CC];
__device__ float g_t1 [MM*CC];
__device__ float g_t2 [MM*CC];

// ---------------- repack q/k projections into NT-GEMM weight layout ----------------
__global__ void repack_kernel(const float* __restrict__ qp, const float* __restrict__ kp,
                              float* __restrict__ W) {
    int idx = blockIdx.x * 256 + threadIdx.x;       // over 256*512
    if (idx >= 256*512) return;
    int n = idx >> 9, d = idx & 511;
    int h = n >> 5, o = n & 31;
    W[idx]              = qp[((h<<9)+d)*32 + o];
    W[(256<<9) + idx]   = kp[((h<<9)+d)*32 + o];
}

// ---------------- generic NT GEMM: C[M,N] = A[M,K] * W[N,K]^T (+ epilogue) ----------------
// mode 0: C = acc ; mode 1: C = acc + R ; mode 2: C = R + silu(acc)
#define BM 64
#define BN 64
#define BK 16
__global__ void gemm_nt(const float* __restrict__ A, const float* __restrict__ W,
                        const float* __restrict__ R, float* __restrict__ C,
                        int M, int N, int K, int mode) {
    __shared__ __align__(16) float As[BK][BM];
    __shared__ __align__(16) float Ws[BK][BN];
    int tid  = threadIdx.x;                // 128 threads
    int row0 = blockIdx.y * BM;
    int col0 = blockIdx.x * BN;
    int tr = tid >> 3;                     // 0..15 -> rows tr*4+i
    int tc = tid & 7;                      // 0..7  -> cols tc*8+j
    float acc[4][8];
#pragma unroll
    for (int i = 0; i < 4; i++)
#pragma unroll
        for (int j = 0; j < 8; j++) acc[i][j] = 0.f;

    for (int k0 = 0; k0 < K; k0 += BK) {
#pragma unroll
        for (int l = 0; l < 2; l++) {
            int f  = tid * 2 + l;          // 0..255 float4 slots
            int r  = f >> 2;               // 0..63
            int kk = (f & 3) * 4;          // 0,4,8,12
            float4 av = *(const float4*)&A[(size_t)(row0 + r) * K + k0 + kk];
            As[kk+0][r] = av.x; As[kk+1][r] = av.y; As[kk+2][r] = av.z; As[kk+3][r] = av.w;
            float4 wv = *(const float4*)&W[(size_t)(col0 + r) * K + k0 + kk];
            Ws[kk+0][r] = wv.x; Ws[kk+1][r] = wv.y; Ws[kk+2][r] = wv.z; Ws[kk+3][r] = wv.w;
        }
        __syncthreads();
#pragma unroll
        for (int kk = 0; kk < BK; kk++) {
            float4 a  = *(const float4*)&As[kk][tr*4];
            float4 w0 = *(const float4*)&Ws[kk][tc*8];
            float4 w1 = *(const float4*)&Ws[kk][tc*8+4];
            float aa[4] = {a.x, a.y, a.z, a.w};
            float ww[8] = {w0.x, w0.y, w0.z, w0.w, w1.x, w1.y, w1.z, w1.w};
#pragma unroll
            for (int i = 0; i < 4; i++)
#pragma unroll
                for (int j = 0; j < 8; j++) acc[i][j] += aa[i] * ww[j];
        }
        __syncthreads();
    }
#pragma unroll
    for (int i = 0; i < 4; i++) {
        int r = row0 + tr*4 + i;
#pragma unroll
        for (int j = 0; j < 8; j++) {
            int c = col0 + tc*8 + j;
            float v = acc[i][j];
            if (mode == 1)      v += R[(size_t)r * N + c];
            else if (mode == 2) v = R[(size_t)r * N + c] + v / (1.f + expf(-v));
            C[(size_t)r * N + c] = v;
        }
    }
}

// ---------------- RoPE + gain, and transpose to [b,h,t,o] ----------------
__global__ void rope_kernel(const float* __restrict__ QK, const float* __restrict__ gain,
                            float* __restrict__ Qo, float* __restrict__ Ko) {
    int bt = blockIdx.x;                    // 0..4095
    int t  = bt & (TT - 1);
    int b  = bt >> 11;
    int tid = threadIdx.x;                  // 0..127
    int h = tid >> 4, i = tid & 15;
    float freq = powf(10000.f, -(float)i * (1.f / 16.f));
    float ang  = (float)t * freq;
    float c = cosf(ang), s = sinf(ang);
    const float* rowq = QK + (size_t)bt * 512 + h * 32;
    const float* rowk = rowq + 256;
    float g  = gain[h];
    float q1 = rowq[i], q2 = rowq[i + 16];
    float k1 = rowk[i], k2 = rowk[i + 16];
    size_t base = ((size_t)(b * HH + h) * TT + t) * DP;
    Qo[base + i]      = (q1 * c - q2 * s) * g;
    Qo[base + i + 16] = (q2 * c + q1 * s) * g;
    Ko[base + i]      = (k1 * c - k2 * s);
    Ko[base + i + 16] = (k2 * c + k1 * s);
}

// ---------------- flash attention (causal) + self-align + transpose-out ----------------
#define FBM 128
#define FBN 64
__global__ void flash_kernel(const float* __restrict__ Q, const float* __restrict__ K,
                             const float* __restrict__ V, float* __restrict__ Y) {
    // grid: (T/FBM, H, B), block 128 threads; thread r owns q-row qt*FBM+r
    int b = blockIdx.z, h = blockIdx.y, qt = blockIdx.x;
    int r = threadIdx.x;
    int i = qt * FBM + r;

    __shared__ __align__(16) float ks[FBN][DP];
    __shared__ __align__(16) float vs[FBN][DH];

    const float* qptr = Q + ((size_t)(b * HH + h) * TT + i) * DP;
    float q[DP];
#pragma unroll
    for (int d = 0; d < DP; d += 4) {
        float4 t4 = *(const float4*)&qptr[d];
        q[d] = t4.x; q[d+1] = t4.y; q[d+2] = t4.z; q[d+3] = t4.w;
    }
    float m = -1e30f, l = 0.f, o[DH];
#pragma unroll
    for (int d = 0; d < DH; d++) o[d] = 0.f;

    const float scale = 0.17677669529663687f;   // 1/sqrt(32)
    int ntiles = qt * 2 + 2;                    // cover j0 <= i_max of this block

    for (int tile = 0; tile < ntiles; tile++) {
        int j0 = tile * FBN;
        // load K tile (64x32): 512 float4, 4 per thread
#pragma unroll
        for (int lod = 0; lod < 4; lod++) {
            int f  = r + lod * 128;             // 0..511
            int jr = f >> 3;
            int d4 = (f & 7) * 4;
            *(float4*)&ks[jr][d4] =
                *(const float4*)&K[((size_t)(b * HH + h) * TT + j0 + jr) * DP + d4];
        }
        // load V tile (64x64): 1024 float4, 8 per thread
#pragma unroll
        for (int lod = 0; lod < 8; lod++) {
            int f  = r + lod * 128;             // 0..1023
            int jr = f >> 4;
            int d4 = (f & 15) * 4;
            *(float4*)&vs[jr][d4] =
                *(const float4*)&V[((size_t)(b * TT) + j0 + jr) * CC + h * DH + d4];
        }
        __syncthreads();

#pragma unroll 4
        for (int j = 0; j < FBN; j++) {
            float s;
            if (j0 + j > i) {
                s = -1e30f;
            } else {
                s = 0.f;
#pragma unroll
                for (int d = 0; d < DP; d += 4) {
                    float4 kv = *(const float4*)&ks[j][d];
                    s += q[d]*kv.x + q[d+1]*kv.y + q[d+2]*kv.z + q[d+3]*kv.w;
                }
                s *= scale;
            }
            if (s > m) {                        // rare rescale
                float cr = expf(m - s);
                m = s; l *= cr;
#pragma unroll
                for (int d = 0; d < DH; d++) o[d] *= cr;
            }
            float p = expf(s - m);
            l += p;
#pragma unroll
            for (int d = 0; d < DH; d += 4) {
                float4 vv = *(const float4*)&vs[j][d];
                o[d]   += p * vv.x; o[d+1] += p * vv.y;
                o[d+2] += p * vv.z; o[d+3] += p * vv.w;
            }
        }
        __syncthreads();
    }

    // normalize + self-align subtraction + write [bt][h*64+d]
    float inv = 1.f / l;
    const float* vptr = V + ((size_t)(b * TT) + i) * CC + h * DH;
    float vr[DH];
    float nrm2 = 0.f;
#pragma unroll
    for (int d = 0; d < DH; d += 4) {
        float4 vv = *(const float4*)&vptr[d];
        vr[d] = vv.x; vr[d+1] = vv.y; vr[d+2] = vv.z; vr[d+3] = vv.w;
        nrm2 += vv.x*vv.x + vv.y*vv.y + vv.z*vv.z + vv.w*vv.w;
    }
    float nrm = fmaxf(sqrtf(nrm2), 1e-12f);
    float dot = 0.f;
#pragma unroll
    for (int d = 0; d < DH; d++) { o[d] *= inv; dot += o[d] * vr[d]; }
    dot /= (nrm * nrm);
    float* yptr = Y + ((size_t)(b * TT) + i) * CC + h * DH;
#pragma unroll
    for (int d = 0; d < DH; d += 4) {
        float4 ov;
        ov.x = o[d]   - dot * vr[d];
        ov.y = o[d+1] - dot * vr[d+1];
        ov.z = o[d+2] - dot * vr[d+2];
        ov.w = o[d+3] - dot * vr[d+3];
        *(float4*)&yptr[d] = ov;
    }
}

// ---------------- layernorm (row of 512) ----------------
__global__ void ln_kernel(const float* __restrict__ X, const float* __restrict__ g,
                          const float* __restrict__ bta, float* __restrict__ O) {
    int row = blockIdx.x;
    int t = threadIdx.x;                    // 128 threads x float4
    __shared__ float red[4], red2[4];
    const float* xp = X + (size_t)row * 512;
    float4 v = *(const float4*)&xp[t * 4];
    float s = v.x + v.y + v.z + v.w;
#pragma unroll
    for (int off = 16; off; off >>= 1) s += __shfl_xor_sync(~0u, s, off);
    if ((t & 31) == 0) red[t >> 5] = s;
    __syncthreads();
    float mean = (red[0] + red[1] + red[2] + red[3]) * (1.f / 512.f);
    float dx = v.x - mean, dy = v.y - mean, dz = v.z - mean, dw = v.w - mean;
    float s2 = dx*dx + dy*dy + dz*dz + dw*dw;
#pragma unroll
    for (int off = 16; off; off >>= 1) s2 += __shfl_xor_sync(~0u, s2, off);
    if ((t & 31) == 0) red2[t >> 5] = s2;
    __syncthreads();
    float var = (red2[0] + red2[1] + red2[2] + red2[3]) * (1.f / 512.f);
    float rsv = rsqrtf(var + 1e-5f);
    float4 gg = *(const float4*)&g[t * 4];
    float4 bb = *(const float4*)&bta[t * 4];
    float4 ov;
    ov.x = dx * rsv * gg.x + bb.x;
    ov.y = dy * rsv * gg.y + bb.y;
    ov.z = dz * rsv * gg.z + bb.z;
    ov.w = dw * rsv * gg.w + bb.w;
    *(float4*)&O[(size_t)row * 512 + t * 4] = ov;
}

// ---------------- rms + out-proj (32) + tanh/temp ----------------
__global__ void final_kernel(const float* __restrict__ X, const float* __restrict__ Wout,
                             const float* __restrict__ ct, float* __restrict__ Z) {
    int row = blockIdx.x;
    int t = threadIdx.x;                    // 256 threads
    __shared__ __align__(16) float xs[512];
    __shared__ float red[8];
    __shared__ float pm[32][9];
    const float* xp = X + (size_t)row * 512;
    float2 v = *(const float2*)&xp[t * 2];
    float s2 = v.x * v.x + v.y * v.y;
#pragma unroll
    for (int off = 16; off; off >>= 1) s2 += __shfl_xor_sync(~0u, s2, off);
    if ((t & 31) == 0) red[t >> 5] = s2;
    __syncthreads();
    float tot = 0.f;
#pragma unroll
    for (int w = 0; w < 8; w++) tot += red[w];
    float rs = rsqrtf(tot * (1.f / 512.f) + 1e-6f);
    xs[t*2] = v.x * rs; xs[t*2+1] = v.y * rs;
    __syncthreads();
    int mi = t >> 3, seg = t & 7;
    const float* wrow = Wout + mi * 512 + seg * 64;
    const float* xseg = xs + seg * 64;
    float acc = 0.f;
#pragma unroll
    for (int d = 0; d < 64; d += 4) {
        float4 wv = *(const float4*)&wrow[d];
        acc += xseg[d]*wv.x + xseg[d+1]*wv.y + xseg[d+2]*wv.z + xseg[d+3]*wv.w;
    }
    pm[mi][seg] = acc;
    __syncthreads();
    if (t < 32) {
        float a = 0.f;
#pragma unroll
        for (int sgi = 0; sgi < 8; sgi++) a += pm[t][sgi];
        float cv = ct[t];
        float sp = (cv > 20.f) ? cv : log1pf(expf(cv));
        Z[(size_t)row * 32 + t] = tanhf(a / (sp + 1e-4f));
    }
}

// ---------------- launch ----------------
extern "C" void kernel_launch(void* const* d_in, const int* in_sizes, int n_in,
                              void* d_out, int out_size) {
    const float* x       = (const float*)d_in[0];
    const float* q_projs = (const float*)d_in[1];
    const float* k_projs = (const float*)d_in[2];
    const float* w_v     = (const float*)d_in[3];
    const float* w_proj  = (const float*)d_in[4];
    const float* q_gain  = (const float*)d_in[5];
    const float* enc_w0  = (const float*)d_in[6];
    const float* ln1g    = (const float*)d_in[7];
    const float* ln1b    = (const float*)d_in[8];
    const float* enc_w1  = (const float*)d_in[9];
    const float* ln2g    = (const float*)d_in[10];
    const float* ln2b    = (const float*)d_in[11];
    const float* enc_w2  = (const float*)d_in[12];
    const float* enc_wo  = (const float*)d_in[13];
    const float* ctemp   = (const float*)d_in[14];
    float* out = (float*)d_out;

    float *p_wqk, *p_qk, *p_q, *p_k, *p_v, *p_y, *p_h, *p_t0, *p_ln, *p_t1, *p_t2;
    cudaGetSymbolAddress((void**)&p_wqk, g_wqk);
    cudaGetSymbolAddress((void**)&p_qk,  g_qk);
    cudaGetSymbolAddress((void**)&p_q,   g_q);
    cudaGetSymbolAddress((void**)&p_k,   g_k);
    cudaGetSymbolAddress((void**)&p_v,   g_v);
    cudaGetSymbolAddress((void**)&p_y,   g_y);
    cudaGetSymbolAddress((void**)&p_h,   g_h);
    cudaGetSymbolAddress((void**)&p_t0,  g_t0);
    cudaGetSymbolAddress((void**)&p_ln,  g_ln);
    cudaGetSymbolAddress((void**)&p_t1,  g_t1);
    cudaGetSymbolAddress((void**)&p_t2,  g_t2);

    dim3 gblk(128), ggrid(512 / BN, MM / BM);

    // 1. repack q/k proj weights
    repack_kernel<<<512, 256>>>(q_projs, k_projs, p_wqk);
    // 2. QK projection (combined): g_qk = X @ Wqk^T
    gemm_nt<<<ggrid, gblk>>>(x, p_wqk, nullptr, p_qk, MM, 512, 512, 0);
    // 3. RoPE + gain + transpose
    rope_kernel<<<MM, 128>>>(p_qk, q_gain, p_q, p_k);
    // 4. V projection: g_v = X @ w_v^T
    gemm_nt<<<ggrid, gblk>>>(x, w_v, nullptr, p_v, MM, 512, 512, 0);
    // 5. flash attention + self-align
    flash_kernel<<<dim3(TT / FBM, HH, BB), 128>>>(p_q, p_k, p_v, p_y);
    // 6. h = x + y @ w_proj^T
    gemm_nt<<<ggrid, gblk>>>(p_y, w_proj, x, p_h, MM, 512, 512, 1);
    // 7. t0 = h @ enc_w0^T
    gemm_nt<<<ggrid, gblk>>>(p_h, enc_w0, nullptr, p_t0, MM, 512, 512, 0);
    // 8. ln = LN(t0)
    ln_kernel<<<MM, 128>>>(p_t0, ln1g, ln1b, p_ln);
    // 9. t1 = h + silu(ln @ enc_w1^T)
    gemm_nt<<<ggrid, gblk>>>(p_ln, enc_w1, p_h, p_t1, MM, 512, 512, 2);
    // 10. ln = LN(t1)
    ln_kernel<<<MM, 128>>>(p_t1, ln2g, ln2b, p_ln);
    // 11. t2 = t1 + silu(ln @ enc_w2^T)
    gemm_nt<<<ggrid, gblk>>>(p_ln, enc_w2, p_t1, p_t2, MM, 512, 512, 2);
    // 12. rms + out proj + tanh
    final_kernel<<<MM, 256>>>(p_t2, enc_wo, ctemp, out);
}

// round 4
// speedup vs baseline: 1.7178x; 1.7178x over previous
#include <cuda_runtime.h>
#include <cuda_bf16.h>
#include <math.h>
#include <stdint.h>

// ---------------- problem constants ----------------
#define BB 2
#define TT 2048
#define CC 512
#define HH 8
#define DP 32
#define DH 64
#define MM (BB*TT)          // 4096 rows

// ---------------- scratch (no allocs allowed) ----------------
__device__ float g_wqk[512*512];
__device__ float g_qk [MM*512];
__device__ float g_q  [BB*HH*TT*DP];
__device__ float g_k  [BB*HH*TT*DP];
__device__ float g_v  [MM*CC];
__device__ float g_y  [MM*CC];
__device__ float g_h  [MM*CC];
__device__ float g_t0 [MM*CC];
__device__ float g_ln [MM*CC];
__device__ float g_t1 [MM*CC];
__device__ float g_t2 [MM*CC];

// ---------------- helpers ----------------
__device__ __forceinline__ uint32_t smem_u32(const void* p) {
    uint32_t a;
    asm("{ .reg .u64 t; cvta.to.shared.u64 t, %1; cvt.u32.u64 %0, t; }" : "=r"(a) : "l"(p));
    return a;
}
__device__ __forceinline__ void ldsm4(uint32_t* r, uint32_t addr) {
    asm volatile("ldmatrix.sync.aligned.m8n8.x4.shared.b16 {%0,%1,%2,%3}, [%4];"
        : "=r"(r[0]), "=r"(r[1]), "=r"(r[2]), "=r"(r[3]) : "r"(addr));
}
__device__ __forceinline__ void ldsm2(uint32_t* r, uint32_t addr) {
    asm volatile("ldmatrix.sync.aligned.m8n8.x2.shared.b16 {%0,%1}, [%2];"
        : "=r"(r[0]), "=r"(r[1]) : "r"(addr));
}
__device__ __forceinline__ void mma16816(float* d, const uint32_t* a, const uint32_t* b) {
    asm volatile("mma.sync.aligned.m16n8k16.row.col.f32.bf16.bf16.f32 "
        "{%0,%1,%2,%3}, {%4,%5,%6,%7}, {%8,%9}, {%0,%1,%2,%3};"
        : "+f"(d[0]), "+f"(d[1]), "+f"(d[2]), "+f"(d[3])
        : "r"(a[0]), "r"(a[1]), "r"(a[2]), "r"(a[3]), "r"(b[0]), "r"(b[1]));
}
__device__ __forceinline__ void split2(float x, float y, uint32_t& hi, uint32_t& lo) {
    __nv_bfloat162 h = __floats2bfloat162_rn(x, y);
    float2 hf = __bfloat1622float2(h);
    __nv_bfloat162 l = __floats2bfloat162_rn(x - hf.x, y - hf.y);
    hi = *(uint32_t*)&h; lo = *(uint32_t*)&l;
}

// ---------------- repack q/k projections into NT weight layout ----------------
__global__ void repack_kernel(const float* __restrict__ qp, const float* __restrict__ kp,
                              float* __restrict__ W) {
    int idx = blockIdx.x * 256 + threadIdx.x;
    if (idx >= 256*512) return;
    int n = idx >> 9, d = idx & 511;
    int h = n >> 5, o = n & 31;
    W[idx]            = qp[((h<<9)+d)*32 + o];
    W[(256<<9) + idx] = kp[((h<<9)+d)*32 + o];
}

// ---------------- bf16x3 mma.sync GEMM: C[4096,512] = A @ W^T (+ epilogue) ----------------
// mode 0: C = acc ; mode 1: C = acc + R ; mode 2: C = R + silu(acc)
// tile 128x128, BK=32 (fp32 in gmem, split to bf16 hi/lo in smem), double buffered.
#define GPAD 40                // bf16 elems per smem row (80B, 16B aligned, LDSM conflict-free)
#define OFF_AH 0
#define OFF_AL 5120
#define OFF_BH 10240
#define OFF_BL 15360
#define GSTG   20480           // bf16 elems per stage

__global__ __launch_bounds__(256, 1)
void gemm_mma(const float* __restrict__ A, const float* __restrict__ W,
              const float* __restrict__ R, float* __restrict__ C, int mode) {
    extern __shared__ __align__(16) char gsm[];
    __nv_bfloat16* s = (__nv_bfloat16*)gsm;
    uint32_t sb0 = smem_u32(s);

    int tid = threadIdx.x;
    int lane = tid & 31, wid = tid >> 5;
    int wm = wid >> 2, wn = wid & 3;           // 2 x 4 warp grid (64 x 32 tiles)
    int row0 = blockIdx.y * 128, col0 = blockIdx.x * 128;

    float acc[4][4][4];
#pragma unroll
    for (int mi = 0; mi < 4; mi++)
#pragma unroll
        for (int ni = 0; ni < 4; ni++)
#pragma unroll
            for (int e = 0; e < 4; e++) acc[mi][ni][e] = 0.f;

    // per-thread load slots: 4 iters, slot = it*256+tid; row = slot>>3, c4 = (slot&7)*4
    float4 la[4], lb[4];
    int lrow[4], lc4[4];
#pragma unroll
    for (int it = 0; it < 4; it++) {
        int slot = it * 256 + tid;
        lrow[it] = slot >> 3;
        lc4[it]  = (slot & 7) << 2;
    }

    // prologue: load k-chunk 0 into stage 0
#pragma unroll
    for (int it = 0; it < 4; it++) {
        la[it] = *(const float4*)&A[(size_t)(row0 + lrow[it]) * 512 + lc4[it]];
        lb[it] = *(const float4*)&W[(size_t)(col0 + lrow[it]) * 512 + lc4[it]];
    }
#pragma unroll
    for (int it = 0; it < 4; it++) {
        int base = lrow[it] * GPAD + lc4[it];
        uint2 h, l;
        split2(la[it].x, la[it].y, h.x, l.x); split2(la[it].z, la[it].w, h.y, l.y);
        *(uint2*)&s[OFF_AH + base] = h; *(uint2*)&s[OFF_AL + base] = l;
        split2(lb[it].x, lb[it].y, h.x, l.x); split2(lb[it].z, lb[it].w, h.y, l.y);
        *(uint2*)&s[OFF_BH + base] = h; *(uint2*)&s[OFF_BL + base] = l;
    }
    __syncthreads();

    for (int k = 0; k < 16; k++) {
        int cur = k & 1;
        if (k < 15) {
            int kc = (k + 1) * 32;
#pragma unroll
            for (int it = 0; it < 4; it++) {
                la[it] = *(const float4*)&A[(size_t)(row0 + lrow[it]) * 512 + kc + lc4[it]];
                lb[it] = *(const float4*)&W[(size_t)(col0 + lrow[it]) * 512 + kc + lc4[it]];
            }
        }
        // ---- compute on stage cur ----
        uint32_t sb = sb0 + (uint32_t)cur * (GSTG * 2);
        int l16 = lane & 15;
        uint32_t arow = (uint32_t)(wm * 64 + (lane & 15)) * GPAD + (uint32_t)((lane >> 4) << 3);
        uint32_t brow = (uint32_t)(wn * 32 + (l16 & 7)) * GPAD + (uint32_t)((l16 >> 3) << 3);
#pragma unroll
        for (int ks = 0; ks < 2; ks++) {
            uint32_t a[4][4], bh[4][2], bl[4][2];
#pragma unroll
            for (int mi = 0; mi < 4; mi++)
                ldsm4(a[mi], sb + 2 * (OFF_AH + arow + (uint32_t)(mi * 16) * GPAD + ks * 16));
#pragma unroll
            for (int ni = 0; ni < 4; ni++) {
                uint32_t ba = sb + 2 * (brow + (uint32_t)(ni * 8) * GPAD + ks * 16);
                ldsm2(bh[ni], ba + 2 * OFF_BH);
                ldsm2(bl[ni], ba + 2 * OFF_BL);
            }
#pragma unroll
            for (int mi = 0; mi < 4; mi++)
#pragma unroll
                for (int ni = 0; ni < 4; ni++) mma16816(acc[mi][ni], a[mi], bh[ni]);
#pragma unroll
            for (int mi = 0; mi < 4; mi++)
#pragma unroll
                for (int ni = 0; ni < 4; ni++) mma16816(acc[mi][ni], a[mi], bl[ni]);
#pragma unroll
            for (int mi = 0; mi < 4; mi++)
                ldsm4(a[mi], sb + 2 * (OFF_AL + arow + (uint32_t)(mi * 16) * GPAD + ks * 16));
#pragma unroll
            for (int mi = 0; mi < 4; mi++)
#pragma unroll
                for (int ni = 0; ni < 4; ni++) mma16816(acc[mi][ni], a[mi], bh[ni]);
        }
        // ---- store next stage ----
        if (k < 15) {
            __nv_bfloat16* sn = s + (size_t)((k + 1) & 1) * GSTG;
#pragma unroll
            for (int it = 0; it < 4; it++) {
                int base = lrow[it] * GPAD + lc4[it];
                uint2 h, l;
                split2(la[it].x, la[it].y, h.x, l.x); split2(la[it].z, la[it].w, h.y, l.y);
                *(uint2*)&sn[OFF_AH + base] = h; *(uint2*)&sn[OFF_AL + base] = l;
                split2(lb[it].x, lb[it].y, h.x, l.x); split2(lb[it].z, lb[it].w, h.y, l.y);
                *(uint2*)&sn[OFF_BH + base] = h; *(uint2*)&sn[OFF_BL + base] = l;
            }
        }
        __syncthreads();
    }

    // ---- epilogue ----
    int gid = lane >> 2, tig = lane & 3;
#pragma unroll
    for (int mi = 0; mi < 4; mi++) {
#pragma unroll
        for (int ni = 0; ni < 4; ni++) {
            int rg = row0 + wm * 64 + mi * 16 + gid;
            int cg = col0 + wn * 32 + ni * 8 + tig * 2;
#pragma unroll
            for (int half = 0; half < 2; half++) {
                int r = rg + half * 8;
                float vx = acc[mi][ni][half * 2], vy = acc[mi][ni][half * 2 + 1];
                size_t gi = (size_t)r * 512 + cg;
                if (mode == 1) {
                    float2 rv = *(const float2*)&R[gi];
                    vx += rv.x; vy += rv.y;
                } else if (mode == 2) {
                    float2 rv = *(const float2*)&R[gi];
                    vx = rv.x + vx / (1.f + __expf(-vx));
                    vy = rv.y + vy / (1.f + __expf(-vy));
                }
                float2 ov; ov.x = vx; ov.y = vy;
                *(float2*)&C[gi] = ov;
            }
        }
    }
}

// ---------------- RoPE + gain, transpose to [b,h,t,o] ----------------
__global__ void rope_kernel(const float* __restrict__ QK, const float* __restrict__ gain,
                            float* __restrict__ Qo, float* __restrict__ Ko) {
    int bt = blockIdx.x;
    int t  = bt & (TT - 1);
    int b  = bt >> 11;
    int tid = threadIdx.x;
    int h = tid >> 4, i = tid & 15;
    float freq = powf(10000.f, -(float)i * (1.f / 16.f));
    float ang  = (float)t * freq;
    float c = cosf(ang), s = sinf(ang);
    const float* rowq = QK + (size_t)bt * 512 + h * 32;
    const float* rowk = rowq + 256;
    float g  = gain[h];
    float q1 = rowq[i], q2 = rowq[i + 16];
    float k1 = rowk[i], k2 = rowk[i + 16];
    size_t base = ((size_t)(b * HH + h) * TT + t) * DP;
    Qo[base + i]      = (q1 * c - q2 * s) * g;
    Qo[base + i + 16] = (q2 * c + q1 * s) * g;
    Ko[base + i]      = (k1 * c - k2 * s);
    Ko[base + i + 16] = (k2 * c + k1 * s);
}

// ---------------- flash attention (causal, split-KV x2) + self-align ----------------
__global__ __launch_bounds__(256, 2)
void flash2(const float* __restrict__ Q, const float* __restrict__ K,
            const float* __restrict__ V, float* __restrict__ Y) {
    extern __shared__ float fsm[];
    int b = blockIdx.z, h = blockIdx.y, qt = blockIdx.x;
    int tid = threadIdx.x;
    int g = tid >> 7, r = tid & 127;
    int i = qt * 128 + r;
    float* ks = fsm + g * 2048;          // [64][32]
    float* vs = fsm + 4096 + g * 4096;   // [64][64]
    float* cm = fsm + 12288;             // [128]
    float* cl = fsm + 12416;             // [128]
    float* co = fsm;                     // [128][64] (reused after compute)

    const float* Kb = K + (size_t)(b * HH + h) * TT * DP;
    const float* Vb = V + (size_t)b * TT * CC + h * DH;
    const float* qptr = Q + (size_t)(b * HH + h) * TT * DP + (size_t)i * DP;

    float q[DP];
#pragma unroll
    for (int d = 0; d < DP; d += 4) {
        float4 t4 = *(const float4*)&qptr[d];
        q[d] = t4.x; q[d+1] = t4.y; q[d+2] = t4.z; q[d+3] = t4.w;
    }
    float m = -1e30f, l = 0.f, o[DH];
#pragma unroll
    for (int d = 0; d < DH; d++) o[d] = 0.f;
    const float scale = 0.17677669529663687f;

    for (int u = 0; u <= qt; u++) {
        int j0 = (2 * u + g) * 64;
#pragma unroll
        for (int it = 0; it < 4; it++) {
            int f = it * 128 + r;
            int jr = f >> 3, d4 = (f & 7) << 2;
            *(float4*)&ks[jr * 32 + d4] = *(const float4*)&Kb[(size_t)(j0 + jr) * DP + d4];
        }
#pragma unroll
        for (int it = 0; it < 8; it++) {
            int f = it * 128 + r;
            int jr = f >> 4, d4 = (f & 15) << 2;
            *(float4*)&vs[jr * 64 + d4] = *(const float4*)&Vb[(size_t)(j0 + jr) * CC + d4];
        }
        __syncthreads();
        int jm = i - j0 + 1;
        if (jm > 64) jm = 64;
#pragma unroll 2
        for (int j = 0; j < jm; j++) {
            float s = 0.f;
#pragma unroll
            for (int d = 0; d < DP; d += 4) {
                float4 kv = *(float4*)&ks[j * 32 + d];
                s += q[d]*kv.x + q[d+1]*kv.y + q[d+2]*kv.z + q[d+3]*kv.w;
            }
            s *= scale;
            if (s > m) {
                float cr = __expf(m - s);
                m = s; l *= cr;
#pragma unroll
                for (int d = 0; d < DH; d++) o[d] *= cr;
            }
            float p = __expf(s - m);
            l += p;
#pragma unroll
            for (int d = 0; d < DH; d += 4) {
                float4 vv = *(float4*)&vs[j * 64 + d];
                o[d]   += p * vv.x; o[d+1] += p * vv.y;
                o[d+2] += p * vv.z; o[d+3] += p * vv.w;
            }
        }
        __syncthreads();
    }

    if (g == 1) {
        cm[r] = m; cl[r] = l;
#pragma unroll
        for (int d = 0; d < DH; d++) co[r * 64 + d] = o[d];
    }
    __syncthreads();
    if (g == 0) {
        float m2 = cm[r], l2 = cl[r];
        float M = fmaxf(m, m2);
        float a1 = __expf(m - M), a2 = __expf(m2 - M);
        float L = l * a1 + l2 * a2;
        float inv = 1.f / L;
        const float* vptr = Vb + (size_t)i * CC;
        float vr[DH];
        float nrm2 = 0.f;
#pragma unroll
        for (int d = 0; d < DH; d += 4) {
            float4 vv = *(const float4*)&vptr[d];
            vr[d] = vv.x; vr[d+1] = vv.y; vr[d+2] = vv.z; vr[d+3] = vv.w;
            nrm2 += vv.x*vv.x + vv.y*vv.y + vv.z*vv.z + vv.w*vv.w;
        }
        float nrm = fmaxf(sqrtf(nrm2), 1e-12f);
        float dot = 0.f;
#pragma unroll
        for (int d = 0; d < DH; d++) {
            o[d] = (o[d] * a1 + co[r * 64 + d] * a2) * inv;
            dot += o[d] * vr[d];
        }
        dot /= (nrm * nrm);
        float* yptr = Y + (size_t)b * TT * CC + (size_t)i * CC + h * DH;
#pragma unroll
        for (int d = 0; d < DH; d += 4) {
            float4 ov;
            ov.x = o[d]   - dot * vr[d];
            ov.y = o[d+1] - dot * vr[d+1];
            ov.z = o[d+2] - dot * vr[d+2];
            ov.w = o[d+3] - dot * vr[d+3];
            *(float4*)&yptr[d] = ov;
        }
    }
}

// ---------------- layernorm (row of 512) ----------------
__global__ void ln_kernel(const float* __restrict__ X, const float* __restrict__ g,
                          const float* __restrict__ bta, float* __restrict__ O) {
    int row = blockIdx.x;
    int t = threadIdx.x;
    __shared__ float red[4], red2[4];
    const float* xp = X + (size_t)row * 512;
    float4 v = *(const float4*)&xp[t * 4];
    float s = v.x + v.y + v.z + v.w;
#pragma unroll
    for (int off = 16; off; off >>= 1) s += __shfl_xor_sync(~0u, s, off);
    if ((t & 31) == 0) red[t >> 5] = s;
    __syncthreads();
    float mean = (red[0] + red[1] + red[2] + red[3]) * (1.f / 512.f);
    float dx = v.x - mean, dy = v.y - mean, dz = v.z - mean, dw = v.w - mean;
    float s2 = dx*dx + dy*dy + dz*dz + dw*dw;
#pragma unroll
    for (int off = 16; off; off >>= 1) s2 += __shfl_xor_sync(~0u, s2, off);
    if ((t & 31) == 0) red2[t >> 5] = s2;
    __syncthreads();
    float var = (red2[0] + red2[1] + red2[2] + red2[3]) * (1.f / 512.f);
    float rsv = rsqrtf(var + 1e-5f);
    float4 gg = *(const float4*)&g[t * 4];
    float4 bb = *(const float4*)&bta[t * 4];
    float4 ov;
    ov.x = dx * rsv * gg.x + bb.x;
    ov.y = dy * rsv * gg.y + bb.y;
    ov.z = dz * rsv * gg.z + bb.z;
    ov.w = dw * rsv * gg.w + bb.w;
    *(float4*)&O[(size_t)row * 512 + t * 4] = ov;
}

// ---------------- rms + out-proj (32) + tanh/temp ----------------
__global__ void final_kernel(const float* __restrict__ X, const float* __restrict__ Wout,
                             const float* __restrict__ ct, float* __restrict__ Z) {
    int row = blockIdx.x;
    int t = threadIdx.x;
    __shared__ __align__(16) float xs[512];
    __shared__ float red[8];
    __shared__ float pm[32][9];
    const float* xp = X + (size_t)row * 512;
    float2 v = *(const float2*)&xp[t * 2];
    float s2 = v.x * v.x + v.y * v.y;
#pragma unroll
    for (int off = 16; off; off >>= 1) s2 += __shfl_xor_sync(~0u, s2, off);
    if ((t & 31) == 0) red[t >> 5] = s2;
    __syncthreads();
    float tot = 0.f;
#pragma unroll
    for (int w = 0; w < 8; w++) tot += red[w];
    float rs = rsqrtf(tot * (1.f / 512.f) + 1e-6f);
    xs[t*2] = v.x * rs; xs[t*2+1] = v.y * rs;
    __syncthreads();
    int mi = t >> 3, seg = t & 7;
    const float* wrow = Wout + mi * 512 + seg * 64;
    const float* xseg = xs + seg * 64;
    float acc = 0.f;
#pragma unroll
    for (int d = 0; d < 64; d += 4) {
        float4 wv = *(const float4*)&wrow[d];
        acc += xseg[d]*wv.x + xseg[d+1]*wv.y + xseg[d+2]*wv.z + xseg[d+3]*wv.w;
    }
    pm[mi][seg] = acc;
    __syncthreads();
    if (t < 32) {
        float a = 0.f;
#pragma unroll
        for (int sgi = 0; sgi < 8; sgi++) a += pm[t][sgi];
        float cv = ct[t];
        float sp = (cv > 20.f) ? cv : log1pf(expf(cv));
        Z[(size_t)row * 32 + t] = tanhf(a / (sp + 1e-4f));
    }
}

// ---------------- launch ----------------
extern "C" void kernel_launch(void* const* d_in, const int* in_sizes, int n_in,
                              void* d_out, int out_size) {
    const float* x       = (const float*)d_in[0];
    const float* q_projs = (const float*)d_in[1];
    const float* k_projs = (const float*)d_in[2];
    const float* w_v     = (const float*)d_in[3];
    const float* w_proj  = (const float*)d_in[4];
    const float* q_gain  = (const float*)d_in[5];
    const float* enc_w0  = (const float*)d_in[6];
    const float* ln1g    = (const float*)d_in[7];
    const float* ln1b    = (const float*)d_in[8];
    const float* enc_w1  = (const float*)d_in[9];
    const float* ln2g    = (const float*)d_in[10];
    const float* ln2b    = (const float*)d_in[11];
    const float* enc_w2  = (const float*)d_in[12];
    const float* enc_wo  = (const float*)d_in[13];
    const float* ctemp   = (const float*)d_in[14];
    float* out = (float*)d_out;

    float *p_wqk, *p_qk, *p_q, *p_k, *p_v, *p_y, *p_h, *p_t0, *p_ln, *p_t1, *p_t2;
    cudaGetSymbolAddress((void**)&p_wqk, g_wqk);
    cudaGetSymbolAddress((void**)&p_qk,  g_qk);
    cudaGetSymbolAddress((void**)&p_q,   g_q);
    cudaGetSymbolAddress((void**)&p_k,   g_k);
    cudaGetSymbolAddress((void**)&p_v,   g_v);
    cudaGetSymbolAddress((void**)&p_y,   g_y);
    cudaGetSymbolAddress((void**)&p_h,   g_h);
    cudaGetSymbolAddress((void**)&p_t0,  g_t0);
    cudaGetSymbolAddress((void**)&p_ln,  g_ln);
    cudaGetSymbolAddress((void**)&p_t1,  g_t1);
    cudaGetSymbolAddress((void**)&p_t2,  g_t2);

    const int GEMM_SMEM  = 2 * GSTG * 2;      // 81920 B (two stages of bf16)
    const int FLASH_SMEM = (12288 + 256) * 4; // 50176 B
    cudaFuncSetAttribute(gemm_mma, cudaFuncAttributeMaxDynamicSharedMemorySize, GEMM_SMEM);
    cudaFuncSetAttribute(flash2,   cudaFuncAttributeMaxDynamicSharedMemorySize, FLASH_SMEM);

    dim3 ggrid(512 / 128, MM / 128);   // (4, 32)

    repack_kernel<<<512, 256>>>(q_projs, k_projs, p_wqk);
    gemm_mma<<<ggrid, 256, GEMM_SMEM>>>(x, p_wqk, nullptr, p_qk, 0);
    rope_kernel<<<MM, 128>>>(p_qk, q_gain, p_q, p_k);
    gemm_mma<<<ggrid, 256, GEMM_SMEM>>>(x, w_v, nullptr, p_v, 0);
    flash2<<<dim3(TT / 128, HH, BB), 256, FLASH_SMEM>>>(p_q, p_k, p_v, p_y);
    gemm_mma<<<ggrid, 256, GEMM_SMEM>>>(p_y, w_proj, x, p_h, 1);
    gemm_mma<<<ggrid, 256, GEMM_SMEM>>>(p_h, enc_w0, nullptr, p_t0, 0);
    ln_kernel<<<MM, 128>>>(p_t0, ln1g, ln1b, p_ln);
    gemm_mma<<<ggrid, 256, GEMM_SMEM>>>(p_ln, enc_w1, p_h, p_t1, 2);
    ln_kernel<<<MM, 128>>>(p_t1, ln2g, ln2b, p_ln);
    gemm_mma<<<ggrid, 256, GEMM_SMEM>>>(p_ln, enc_w2, p_t1, p_t2, 2);
    final_kernel<<<MM, 256>>>(p_t2, enc_wo, ctemp, out);
}

// round 6
// speedup vs baseline: 3.3382x; 1.9433x over previous
#include <cuda_runtime.h>
#include <cuda_bf16.h>
#include <math.h>
#include <stdint.h>

// ---------------- problem constants ----------------
#define BB 2
#define TT 2048
#define CC 512
#define HH 8
#define DP 32
#define DH 64
#define MM (BB*TT)          // 4096 rows

// ---------------- scratch (no allocs allowed) ----------------
__device__ float g_wqk[512*512];
__device__ float g_qk [MM*512];
__device__ float g_q  [BB*HH*TT*DP];
__device__ float g_k  [BB*HH*TT*DP];
__device__ float g_v  [MM*CC];
__device__ float g_y  [MM*CC];
__device__ float g_h  [MM*CC];
__device__ float g_t0 [MM*CC];
__device__ float g_ln [MM*CC];
__device__ float g_t1 [MM*CC];
__device__ float g_t2 [MM*CC];

// ---------------- helpers ----------------
__device__ __forceinline__ uint32_t smem_u32(const void* p) {
    uint32_t a;
    asm("{ .reg .u64 t; cvta.to.shared.u64 t, %1; cvt.u32.u64 %0, t; }" : "=r"(a) : "l"(p));
    return a;
}
__device__ __forceinline__ void ldsm4(uint32_t* r, uint32_t addr) {
    asm volatile("ldmatrix.sync.aligned.m8n8.x4.shared.b16 {%0,%1,%2,%3}, [%4];"
        : "=r"(r[0]), "=r"(r[1]), "=r"(r[2]), "=r"(r[3]) : "r"(addr));
}
__device__ __forceinline__ void ldsm4t(uint32_t* r, uint32_t addr) {
    asm volatile("ldmatrix.sync.aligned.m8n8.x4.trans.shared.b16 {%0,%1,%2,%3}, [%4];"
        : "=r"(r[0]), "=r"(r[1]), "=r"(r[2]), "=r"(r[3]) : "r"(addr));
}
__device__ __forceinline__ void ldsm2(uint32_t* r, uint32_t addr) {
    asm volatile("ldmatrix.sync.aligned.m8n8.x2.shared.b16 {%0,%1}, [%2];"
        : "=r"(r[0]), "=r"(r[1]) : "r"(addr));
}
__device__ __forceinline__ void mma16816(float* d, const uint32_t* a, const uint32_t* b) {
    asm volatile("mma.sync.aligned.m16n8k16.row.col.f32.bf16.bf16.f32 "
        "{%0,%1,%2,%3}, {%4,%5,%6,%7}, {%8,%9}, {%0,%1,%2,%3};"
        : "+f"(d[0]), "+f"(d[1]), "+f"(d[2]), "+f"(d[3])
        : "r"(a[0]), "r"(a[1]), "r"(a[2]), "r"(a[3]), "r"(b[0]), "r"(b[1]));
}
__device__ __forceinline__ void split2(float x, float y, uint32_t& hi, uint32_t& lo) {
    __nv_bfloat162 h = __floats2bfloat162_rn(x, y);
    float2 hf = __bfloat1622float2(h);
    __nv_bfloat162 l = __floats2bfloat162_rn(x - hf.x, y - hf.y);
    hi = *(uint32_t*)&h; lo = *(uint32_t*)&l;
}

// ---------------- repack q/k projections into NT weight layout ----------------
__global__ void repack_kernel(const float* __restrict__ qp, const float* __restrict__ kp,
                              float* __restrict__ W) {
    int idx = blockIdx.x * 256 + threadIdx.x;
    if (idx >= 256*512) return;
    int n = idx >> 9, d = idx & 511;
    int h = n >> 5, o = n & 31;
    W[idx]            = qp[((h<<9)+d)*32 + o];
    W[(256<<9) + idx] = kp[((h<<9)+d)*32 + o];
}

// ---------------- bf16x3 mma.sync GEMM (unchanged from R4) ----------------
#define GPAD 40
#define OFF_AH 0
#define OFF_AL 5120
#define OFF_BH 10240
#define OFF_BL 15360
#define GSTG   20480

__global__ __launch_bounds__(256, 1)
void gemm_mma(const float* __restrict__ A, const float* __restrict__ W,
              const float* __restrict__ R, float* __restrict__ C, int mode) {
    extern __shared__ __align__(16) char gsm[];
    __nv_bfloat16* s = (__nv_bfloat16*)gsm;
    uint32_t sb0 = smem_u32(s);

    int tid = threadIdx.x;
    int lane = tid & 31, wid = tid >> 5;
    int wm = wid >> 2, wn = wid & 3;
    int row0 = blockIdx.y * 128, col0 = blockIdx.x * 128;

    float acc[4][4][4];
#pragma unroll
    for (int mi = 0; mi < 4; mi++)
#pragma unroll
        for (int ni = 0; ni < 4; ni++)
#pragma unroll
            for (int e = 0; e < 4; e++) acc[mi][ni][e] = 0.f;

    float4 la[4], lb[4];
    int lrow[4], lc4[4];
#pragma unroll
    for (int it = 0; it < 4; it++) {
        int slot = it * 256 + tid;
        lrow[it] = slot >> 3;
        lc4[it]  = (slot & 7) << 2;
    }

#pragma unroll
    for (int it = 0; it < 4; it++) {
        la[it] = *(const float4*)&A[(size_t)(row0 + lrow[it]) * 512 + lc4[it]];
        lb[it] = *(const float4*)&W[(size_t)(col0 + lrow[it]) * 512 + lc4[it]];
    }
#pragma unroll
    for (int it = 0; it < 4; it++) {
        int base = lrow[it] * GPAD + lc4[it];
        uint2 h, l;
        split2(la[it].x, la[it].y, h.x, l.x); split2(la[it].z, la[it].w, h.y, l.y);
        *(uint2*)&s[OFF_AH + base] = h; *(uint2*)&s[OFF_AL + base] = l;
        split2(lb[it].x, lb[it].y, h.x, l.x); split2(lb[it].z, lb[it].w, h.y, l.y);
        *(uint2*)&s[OFF_BH + base] = h; *(uint2*)&s[OFF_BL + base] = l;
    }
    __syncthreads();

    for (int k = 0; k < 16; k++) {
        int cur = k & 1;
        if (k < 15) {
            int kc = (k + 1) * 32;
#pragma unroll
            for (int it = 0; it < 4; it++) {
                la[it] = *(const float4*)&A[(size_t)(row0 + lrow[it]) * 512 + kc + lc4[it]];
                lb[it] = *(const float4*)&W[(size_t)(col0 + lrow[it]) * 512 + kc + lc4[it]];
            }
        }
        uint32_t sb = sb0 + (uint32_t)cur * (GSTG * 2);
        int l16 = lane & 15;
        uint32_t arow = (uint32_t)(wm * 64 + (lane & 15)) * GPAD + (uint32_t)((lane >> 4) << 3);
        uint32_t brow = (uint32_t)(wn * 32 + (l16 & 7)) * GPAD + (uint32_t)((l16 >> 3) << 3);
#pragma unroll
        for (int ks = 0; ks < 2; ks++) {
            uint32_t a[4][4], bh[4][2], bl[4][2];
#pragma unroll
            for (int mi = 0; mi < 4; mi++)
                ldsm4(a[mi], sb + 2 * (OFF_AH + arow + (uint32_t)(mi * 16) * GPAD + ks * 16));
#pragma unroll
            for (int ni = 0; ni < 4; ni++) {
                uint32_t ba = sb + 2 * (brow + (uint32_t)(ni * 8) * GPAD + ks * 16);
                ldsm2(bh[ni], ba + 2 * OFF_BH);
                ldsm2(bl[ni], ba + 2 * OFF_BL);
            }
#pragma unroll
            for (int mi = 0; mi < 4; mi++)
#pragma unroll
                for (int ni = 0; ni < 4; ni++) mma16816(acc[mi][ni], a[mi], bh[ni]);
#pragma unroll
            for (int mi = 0; mi < 4; mi++)
#pragma unroll
                for (int ni = 0; ni < 4; ni++) mma16816(acc[mi][ni], a[mi], bl[ni]);
#pragma unroll
            for (int mi = 0; mi < 4; mi++)
                ldsm4(a[mi], sb + 2 * (OFF_AL + arow + (uint32_t)(mi * 16) * GPAD + ks * 16));
#pragma unroll
            for (int mi = 0; mi < 4; mi++)
#pragma unroll
                for (int ni = 0; ni < 4; ni++) mma16816(acc[mi][ni], a[mi], bh[ni]);
        }
        if (k < 15) {
            __nv_bfloat16* sn = s + (size_t)((k + 1) & 1) * GSTG;
#pragma unroll
            for (int it = 0; it < 4; it++) {
                int base = lrow[it] * GPAD + lc4[it];
                uint2 h, l;
                split2(la[it].x, la[it].y, h.x, l.x); split2(la[it].z, la[it].w, h.y, l.y);
                *(uint2*)&sn[OFF_AH + base] = h; *(uint2*)&sn[OFF_AL + base] = l;
                split2(lb[it].x, lb[it].y, h.x, l.x); split2(lb[it].z, lb[it].w, h.y, l.y);
                *(uint2*)&sn[OFF_BH + base] = h; *(uint2*)&sn[OFF_BL + base] = l;
            }
        }
        __syncthreads();
    }

    int gid = lane >> 2, tig = lane & 3;
#pragma unroll
    for (int mi = 0; mi < 4; mi++) {
#pragma unroll
        for (int ni = 0; ni < 4; ni++) {
            int rg = row0 + wm * 64 + mi * 16 + gid;
            int cg = col0 + wn * 32 + ni * 8 + tig * 2;
#pragma unroll
            for (int half = 0; half < 2; half++) {
                int r = rg + half * 8;
                float vx = acc[mi][ni][half * 2], vy = acc[mi][ni][half * 2 + 1];
                size_t gi = (size_t)r * 512 + cg;
                if (mode == 1) {
                    float2 rv = *(const float2*)&R[gi];
                    vx += rv.x; vy += rv.y;
                } else if (mode == 2) {
                    float2 rv = *(const float2*)&R[gi];
                    vx = rv.x + vx / (1.f + __expf(-vx));
                    vy = rv.y + vy / (1.f + __expf(-vy));
                }
                float2 ov; ov.x = vx; ov.y = vy;
                *(float2*)&C[gi] = ov;
            }
        }
    }
}

// ---------------- RoPE + gain (+ attention scale folded into q) ----------------
__global__ void rope_kernel(const float* __restrict__ QK, const float* __restrict__ gain,
                            float* __restrict__ Qo, float* __restrict__ Ko) {
    int bt = blockIdx.x;
    int t  = bt & (TT - 1);
    int b  = bt >> 11;
    int tid = threadIdx.x;
    int h = tid >> 4, i = tid & 15;
    float freq = powf(10000.f, -(float)i * (1.f / 16.f));
    float ang  = (float)t * freq;
    float c = cosf(ang), s = sinf(ang);
    const float* rowq = QK + (size_t)bt * 512 + h * 32;
    const float* rowk = rowq + 256;
    float g  = gain[h] * 0.17677669529663687f;   // gain * 1/sqrt(32)
    float q1 = rowq[i], q2 = rowq[i + 16];
    float k1 = rowk[i], k2 = rowk[i + 16];
    size_t base = ((size_t)(b * HH + h) * TT + t) * DP;
    Qo[base + i]      = (q1 * c - q2 * s) * g;
    Qo[base + i + 16] = (q2 * c + q1 * s) * g;
    Ko[base + i]      = (k1 * c - k2 * s);
    Ko[base + i + 16] = (k2 * c + k1 * s);
}

// ---------------- flash attention via mma.sync (causal) + self-align ----------------
// block: 256 thr (8 warps), q-tile 128 rows (16/warp), kv-tile 64.
// smem (bf16 elems): Kh@0 [64][40], Kl@2560, Vh@5120 [64][72], Vl@9728 ; total 14336
// Q staging reuses offsets 0..10240 before the main loop.
#define FKP 40      // K smem pitch (80B = 5*16)
#define FVP 72      // V smem pitch (144B = 9*16)
#define SKH 0
#define SKL 2560
#define SVH 5120
#define SVL 9728

__global__ __launch_bounds__(256, 1)
void flash_mma(const float* __restrict__ Q, const float* __restrict__ K,
               const float* __restrict__ V, float* __restrict__ Y) {
    extern __shared__ __align__(16) __nv_bfloat16 fs[];
    uint32_t sb = smem_u32(fs);

    int b = blockIdx.z, h = blockIdx.y;
    int qt = (int)gridDim.x - 1 - (int)blockIdx.x;     // heavy blocks first
    int tid = threadIdx.x, lane = tid & 31, wid = tid >> 5;
    int gid = lane >> 2, tig = lane & 3;
    int qrow0 = qt * 128;

    const float* Qb = Q + ((size_t)(b * HH + h) * TT + qrow0) * DP;
    const float* Kb = K + (size_t)(b * HH + h) * TT * DP;
    const float* Vb = V + (size_t)b * TT * CC + h * DH;

    // ---- stage Q tile (128x32) into smem as bf16 hi/lo, then load A fragments ----
#pragma unroll
    for (int it = 0; it < 4; it++) {
        int slot = it * 256 + tid;                 // 1024 float4 slots
        int row = slot >> 3, c4 = (slot & 7) << 2;
        float4 v = *(const float4*)&Qb[(size_t)row * DP + c4];
        uint2 hh, ll;
        split2(v.x, v.y, hh.x, ll.x); split2(v.z, v.w, hh.y, ll.y);
        *(uint2*)&fs[row * FKP + c4] = hh;
        *(uint2*)&fs[5120 + row * FKP + c4] = ll;
    }
    __syncthreads();
    uint32_t qh[2][4], ql[2][4];
    {
        uint32_t arow = (uint32_t)(wid * 16 + (lane & 15)) * FKP + (uint32_t)((lane >> 4) << 3);
#pragma unroll
        for (int ks = 0; ks < 2; ks++) {
            ldsm4(qh[ks], sb + 2 * (arow + ks * 16));
            ldsm4(ql[ks], sb + 2 * (5120 + arow + ks * 16));
        }
    }
    __syncthreads();

    float m0 = -1e30f, m1 = -1e30f, l0 = 0.f, l1 = 0.f;
    float o[8][4];
#pragma unroll
    for (int nt = 0; nt < 8; nt++)
#pragma unroll
        for (int e = 0; e < 4; e++) o[nt][e] = 0.f;

    int wmax = qrow0 + wid * 16 + 15;
    int ntiles = 2 * qt + 2;

    for (int t = 0; t < ntiles; t++) {
        int j0 = t * 64;
        // ---- cooperative load K (64x32) + V (64x64), fp32 -> bf16 hi/lo ----
#pragma unroll
        for (int it = 0; it < 2; it++) {
            int slot = it * 256 + tid;             // 512 float4 slots
            int row = slot >> 3, c4 = (slot & 7) << 2;
            float4 v = *(const float4*)&Kb[(size_t)(j0 + row) * DP + c4];
            uint2 hh, ll;
            split2(v.x, v.y, hh.x, ll.x); split2(v.z, v.w, hh.y, ll.y);
            *(uint2*)&fs[SKH + row * FKP + c4] = hh;
            *(uint2*)&fs[SKL + row * FKP + c4] = ll;
        }
#pragma unroll
        for (int it = 0; it < 4; it++) {
            int slot = it * 256 + tid;             // 1024 float4 slots
            int row = slot >> 4, c4 = (slot & 15) << 2;
            float4 v = *(const float4*)&Vb[(size_t)(j0 + row) * CC + c4];
            uint2 hh, ll;
            split2(v.x, v.y, hh.x, ll.x); split2(v.z, v.w, hh.y, ll.y);
            *(uint2*)&fs[SVH + row * FVP + c4] = hh;
            *(uint2*)&fs[SVL + row * FVP + c4] = ll;
        }
        __syncthreads();

        if (j0 <= wmax) {
            // ---- QK^T: scores 16x64 per warp ----
            float sc[8][4];
#pragma unroll
            for (int nt = 0; nt < 8; nt++)
#pragma unroll
                for (int e = 0; e < 4; e++) sc[nt][e] = 0.f;
            uint32_t kbase = (uint32_t)(lane & 7) * FKP + (uint32_t)(((lane >> 3) & 3) << 3);
#pragma unroll
            for (int nt = 0; nt < 8; nt++) {
                uint32_t kbh[4], kbl[4];
                uint32_t ka = sb + 2 * (kbase + (uint32_t)(nt * 8) * FKP);
                ldsm4(kbh, ka + 2 * SKH);
                ldsm4(kbl, ka + 2 * SKL);
                mma16816(sc[nt], qh[0], kbh);
                mma16816(sc[nt], qh[1], kbh + 2);
                mma16816(sc[nt], qh[0], kbl);
                mma16816(sc[nt], qh[1], kbl + 2);
                mma16816(sc[nt], ql[0], kbh);
                mma16816(sc[nt], ql[1], kbh + 2);
            }
            // ---- causal mask (only near diagonal) ----
            if (j0 + 63 > qrow0 + wid * 16) {
                int r0 = qrow0 + wid * 16 + gid, r1 = r0 + 8;
#pragma unroll
                for (int nt = 0; nt < 8; nt++) {
                    int c = j0 + nt * 8 + tig * 2;
                    if (c > r0)     sc[nt][0] = -1e30f;
                    if (c + 1 > r0) sc[nt][1] = -1e30f;
                    if (c > r1)     sc[nt][2] = -1e30f;
                    if (c + 1 > r1) sc[nt][3] = -1e30f;
                }
            }
            // ---- online softmax ----
            float mx0 = -1e30f, mx1 = -1e30f;
#pragma unroll
            for (int nt = 0; nt < 8; nt++) {
                mx0 = fmaxf(mx0, fmaxf(sc[nt][0], sc[nt][1]));
                mx1 = fmaxf(mx1, fmaxf(sc[nt][2], sc[nt][3]));
            }
            mx0 = fmaxf(mx0, __shfl_xor_sync(~0u, mx0, 1));
            mx0 = fmaxf(mx0, __shfl_xor_sync(~0u, mx0, 2));
            mx1 = fmaxf(mx1, __shfl_xor_sync(~0u, mx1, 1));
            mx1 = fmaxf(mx1, __shfl_xor_sync(~0u, mx1, 2));
            float mn0 = fmaxf(m0, mx0), mn1 = fmaxf(m1, mx1);
            float cr0 = __expf(m0 - mn0), cr1 = __expf(m1 - mn1);
            m0 = mn0; m1 = mn1;
            float ls0 = 0.f, ls1 = 0.f;
#pragma unroll
            for (int nt = 0; nt < 8; nt++) {
                sc[nt][0] = __expf(sc[nt][0] - m0);
                sc[nt][1] = __expf(sc[nt][1] - m0);
                sc[nt][2] = __expf(sc[nt][2] - m1);
                sc[nt][3] = __expf(sc[nt][3] - m1);
                ls0 += sc[nt][0] + sc[nt][1];
                ls1 += sc[nt][2] + sc[nt][3];
            }
            l0 = l0 * cr0 + ls0;
            l1 = l1 * cr1 + ls1;
#pragma unroll
            for (int nt = 0; nt < 8; nt++) {
                o[nt][0] *= cr0; o[nt][1] *= cr0;
                o[nt][2] *= cr1; o[nt][3] *= cr1;
            }
            // ---- P @ V ----
            uint32_t vbase = (uint32_t)(lane & 15) * FVP + (uint32_t)((lane >> 4) << 3);
#pragma unroll
            for (int kk = 0; kk < 4; kk++) {
                uint32_t ah[4], al[4];
                split2(sc[2*kk][0],   sc[2*kk][1],   ah[0], al[0]);
                split2(sc[2*kk][2],   sc[2*kk][3],   ah[1], al[1]);
                split2(sc[2*kk+1][0], sc[2*kk+1][1], ah[2], al[2]);
                split2(sc[2*kk+1][2], sc[2*kk+1][3], ah[3], al[3]);
#pragma unroll
                for (int nv = 0; nv < 4; nv++) {
                    uint32_t vbh[4], vbl[4];
                    uint32_t va = sb + 2 * (vbase + (uint32_t)(kk * 16) * FVP + (uint32_t)(nv * 16));
                    ldsm4t(vbh, va + 2 * SVH);
                    ldsm4t(vbl, va + 2 * SVL);
                    mma16816(o[2*nv],     ah, vbh);
                    mma16816(o[2*nv + 1], ah, vbh + 2);
                    mma16816(o[2*nv],     ah, vbl);
                    mma16816(o[2*nv + 1], ah, vbl + 2);
                    mma16816(o[2*nv],     al, vbh);
                    mma16816(o[2*nv + 1], al, vbh + 2);
                }
            }
        }
        __syncthreads();
    }

    // ---- finalize: reduce l across quad, normalize, self-align, write ----
    l0 += __shfl_xor_sync(~0u, l0, 1); l0 += __shfl_xor_sync(~0u, l0, 2);
    l1 += __shfl_xor_sync(~0u, l1, 1); l1 += __shfl_xor_sync(~0u, l1, 2);
    float inv0 = 1.f / l0, inv1 = 1.f / l1;
#pragma unroll
    for (int nt = 0; nt < 8; nt++) {
        o[nt][0] *= inv0; o[nt][1] *= inv0;
        o[nt][2] *= inv1; o[nt][3] *= inv1;
    }
    int i0 = qrow0 + wid * 16 + gid, i1 = i0 + 8;
    float dot0 = 0.f, n20 = 0.f, dot1 = 0.f, n21 = 0.f;
#pragma unroll
    for (int nt = 0; nt < 8; nt++) {
        int d = nt * 8 + tig * 2;
        float2 v0 = *(const float2*)&Vb[(size_t)i0 * CC + d];
        float2 v1 = *(const float2*)&Vb[(size_t)i1 * CC + d];
        dot0 += o[nt][0] * v0.x + o[nt][1] * v0.y;
        n20  += v0.x * v0.x + v0.y * v0.y;
        dot1 += o[nt][2] * v1.x + o[nt][3] * v1.y;
        n21  += v1.x * v1.x + v1.y * v1.y;
    }
    dot0 += __shfl_xor_sync(~0u, dot0, 1); dot0 += __shfl_xor_sync(~0u, dot0, 2);
    n20  += __shfl_xor_sync(~0u, n20, 1);  n20  += __shfl_xor_sync(~0u, n20, 2);
    dot1 += __shfl_xor_sync(~0u, dot1, 1); dot1 += __shfl_xor_sync(~0u, dot1, 2);
    n21  += __shfl_xor_sync(~0u, n21, 1);  n21  += __shfl_xor_sync(~0u, n21, 2);
    float nr0 = fmaxf(sqrtf(n20), 1e-12f);
    float nr1 = fmaxf(sqrtf(n21), 1e-12f);
    dot0 /= (nr0 * nr0);
    dot1 /= (nr1 * nr1);
    float* Y0 = Y + (size_t)(b * TT + i0) * CC + h * DH;
    float* Y1 = Y + (size_t)(b * TT + i1) * CC + h * DH;
#pragma unroll
    for (int nt = 0; nt < 8; nt++) {
        int d = nt * 8 + tig * 2;
        float2 v0 = *(const float2*)&Vb[(size_t)i0 * CC + d];
        float2 v1 = *(const float2*)&Vb[(size_t)i1 * CC + d];
        float2 y0, y1;
        y0.x = o[nt][0] - dot0 * v0.x; y0.y = o[nt][1] - dot0 * v0.y;
        y1.x = o[nt][2] - dot1 * v1.x; y1.y = o[nt][3] - dot1 * v1.y;
        *(float2*)&Y0[d] = y0;
        *(float2*)&Y1[d] = y1;
    }
}

// ---------------- layernorm (row of 512) ----------------
__global__ void ln_kernel(const float* __restrict__ X, const float* __restrict__ g,
                          const float* __restrict__ bta, float* __restrict__ O) {
    int row = blockIdx.x;
    int t = threadIdx.x;
    __shared__ float red[4], red2[4];
    const float* xp = X + (size_t)row * 512;
    float4 v = *(const float4*)&xp[t * 4];
    float s = v.x + v.y + v.z + v.w;
#pragma unroll
    for (int off = 16; off; off >>= 1) s += __shfl_xor_sync(~0u, s, off);
    if ((t & 31) == 0) red[t >> 5] = s;
    __syncthreads();
    float mean = (red[0] + red[1] + red[2] + red[3]) * (1.f / 512.f);
    float dx = v.x - mean, dy = v.y - mean, dz = v.z - mean, dw = v.w - mean;
    float s2 = dx*dx + dy*dy + dz*dz + dw*dw;
#pragma unroll
    for (int off = 16; off; off >>= 1) s2 += __shfl_xor_sync(~0u, s2, off);
    if ((t & 31) == 0) red2[t >> 5] = s2;
    __syncthreads();
    float var = (red2[0] + red2[1] + red2[2] + red2[3]) * (1.f / 512.f);
    float rsv = rsqrtf(var + 1e-5f);
    float4 gg = *(const float4*)&g[t * 4];
    float4 bb = *(const float4*)&bta[t * 4];
    float4 ov;
    ov.x = dx * rsv * gg.x + bb.x;
    ov.y = dy * rsv * gg.y + bb.y;
    ov.z = dz * rsv * gg.z + bb.z;
    ov.w = dw * rsv * gg.w + bb.w;
    *(float4*)&O[(size_t)row * 512 + t * 4] = ov;
}

// ---------------- rms + out-proj (32) + tanh/temp ----------------
__global__ void final_kernel(const float* __restrict__ X, const float* __restrict__ Wout,
                             const float* __restrict__ ct, float* __restrict__ Z) {
    int row = blockIdx.x;
    int t = threadIdx.x;
    __shared__ __align__(16) float xs[512];
    __shared__ float red[8];
    __shared__ float pm[32][9];
    const float* xp = X + (size_t)row * 512;
    float2 v = *(const float2*)&xp[t * 2];
    float s2 = v.x * v.x + v.y * v.y;
#pragma unroll
    for (int off = 16; off; off >>= 1) s2 += __shfl_xor_sync(~0u, s2, off);
    if ((t & 31) == 0) red[t >> 5] = s2;
    __syncthreads();
    float tot = 0.f;
#pragma unroll
    for (int w = 0; w < 8; w++) tot += red[w];
    float rs = rsqrtf(tot * (1.f / 512.f) + 1e-6f);
    xs[t*2] = v.x * rs; xs[t*2+1] = v.y * rs;
    __syncthreads();
    int mi = t >> 3, seg = t & 7;
    const float* wrow = Wout + mi * 512 + seg * 64;
    const float* xseg = xs + seg * 64;
    float acc = 0.f;
#pragma unroll
    for (int d = 0; d < 64; d += 4) {
        float4 wv = *(const float4*)&wrow[d];
        acc += xseg[d]*wv.x + xseg[d+1]*wv.y + xseg[d+2]*wv.z + xseg[d+3]*wv.w;
    }
    pm[mi][seg] = acc;
    __syncthreads();
    if (t < 32) {
        float a = 0.f;
#pragma unroll
        for (int sgi = 0; sgi < 8; sgi++) a += pm[t][sgi];
        float cv = ct[t];
        float sp = (cv > 20.f) ? cv : log1pf(expf(cv));
        Z[(size_t)row * 32 + t] = tanhf(a / (sp + 1e-4f));
    }
}

// ---------------- launch ----------------
extern "C" void kernel_launch(void* const* d_in, const int* in_sizes, int n_in,
                              void* d_out, int out_size) {
    const float* x       = (const float*)d_in[0];
    const float* q_projs = (const float*)d_in[1];
    const float* k_projs = (const float*)d_in[2];
    const float* w_v     = (const float*)d_in[3];
    const float* w_proj  = (const float*)d_in[4];
    const float* q_gain  = (const float*)d_in[5];
    const float* enc_w0  = (const float*)d_in[6];
    const float* ln1g    = (const float*)d_in[7];
    const float* ln1b    = (const float*)d_in[8];
    const float* enc_w1  = (const float*)d_in[9];
    const float* ln2g    = (const float*)d_in[10];
    const float* ln2b    = (const float*)d_in[11];
    const float* enc_w2  = (const float*)d_in[12];
    const float* enc_wo  = (const float*)d_in[13];
    const float* ctemp   = (const float*)d_in[14];
    float* out = (float*)d_out;

    float *p_wqk, *p_qk, *p_q, *p_k, *p_v, *p_y, *p_h, *p_t0, *p_ln, *p_t1, *p_t2;
    cudaGetSymbolAddress((void**)&p_wqk, g_wqk);
    cudaGetSymbolAddress((void**)&p_qk,  g_qk);
    cudaGetSymbolAddress((void**)&p_q,   g_q);
    cudaGetSymbolAddress((void**)&p_k,   g_k);
    cudaGetSymbolAddress((void**)&p_v,   g_v);
    cudaGetSymbolAddress((void**)&p_y,   g_y);
    cudaGetSymbolAddress((void**)&p_h,   g_h);
    cudaGetSymbolAddress((void**)&p_t0,  g_t0);
    cudaGetSymbolAddress((void**)&p_ln,  g_ln);
    cudaGetSymbolAddress((void**)&p_t1,  g_t1);
    cudaGetSymbolAddress((void**)&p_t2,  g_t2);

    const int GEMM_SMEM  = 2 * GSTG * 2;   // 81920 B
    const int FLASH_SMEM = 14336 * 2;      // 28672 B
    cudaFuncSetAttribute(gemm_mma,  cudaFuncAttributeMaxDynamicSharedMemorySize, GEMM_SMEM);
    cudaFuncSetAttribute(flash_mma, cudaFuncAttributeMaxDynamicSharedMemorySize, FLASH_SMEM);

    dim3 ggrid(512 / 128, MM / 128);   // (4, 32)

    repack_kernel<<<512, 256>>>(q_projs, k_projs, p_wqk);
    gemm_mma<<<ggrid, 256, GEMM_SMEM>>>(x, p_wqk, nullptr, p_qk, 0);
    rope_kernel<<<MM, 128>>>(p_qk, q_gain, p_q, p_k);
    gemm_mma<<<ggrid, 256, GEMM_SMEM>>>(x, w_v, nullptr, p_v, 0);
    flash_mma<<<dim3(TT / 128, HH, BB), 256, FLASH_SMEM>>>(p_q, p_k, p_v, p_y);
    gemm_mma<<<ggrid, 256, GEMM_SMEM>>>(p_y, w_proj, x, p_h, 1);
    gemm_mma<<<ggrid, 256, GEMM_SMEM>>>(p_h, enc_w0, nullptr, p_t0, 0);
    ln_kernel<<<MM, 128>>>(p_t0, ln1g, ln1b, p_ln);
    gemm_mma<<<ggrid, 256, GEMM_SMEM>>>(p_ln, enc_w1, p_h, p_t1, 2);
    ln_kernel<<<MM, 128>>>(p_t1, ln2g, ln2b, p_ln);
    gemm_mma<<<ggrid, 256, GEMM_SMEM>>>(p_ln, enc_w2, p_t1, p_t2, 2);
    final_kernel<<<MM, 256>>>(p_t2, enc_wo, ctemp, out);
}

// round 8
// speedup vs baseline: 3.3944x; 1.0169x over previous
#include <cuda_runtime.h>
#include <cuda_bf16.h>
#include <math.h>
#include <stdint.h>

// ---------------- problem constants ----------------
#define BB 2
#define TT 2048
#define CC 512
#define HH 8
#define DP 32
#define DH 64
#define MM (BB*TT)          // 4096 rows

// ---------------- scratch (no allocs allowed) ----------------
__device__ float g_wqk[512*512];
__device__ float g_qk [MM*512];
__device__ float g_v  [MM*CC];
__device__ float g_y  [MM*CC];
__device__ float g_h  [MM*CC];
__device__ float g_t0 [MM*CC];
__device__ float g_ln [MM*CC];
__device__ float g_t1 [MM*CC];
__device__ float g_t2 [MM*CC];
__device__ __nv_bfloat16 g_qh[BB*HH*TT*DP];
__device__ __nv_bfloat16 g_ql[BB*HH*TT*DP];
__device__ __nv_bfloat16 g_kh[BB*HH*TT*DP];
__device__ __nv_bfloat16 g_kl[BB*HH*TT*DP];
__device__ __nv_bfloat16 g_vh[MM*CC];
__device__ __nv_bfloat16 g_vl[MM*CC];

// ---------------- helpers ----------------
__device__ __forceinline__ uint32_t smem_u32(const void* p) {
    uint32_t a;
    asm("{ .reg .u64 t; cvta.to.shared.u64 t, %1; cvt.u32.u64 %0, t; }" : "=r"(a) : "l"(p));
    return a;
}
__device__ __forceinline__ void ldsm4(uint32_t* r, uint32_t addr) {
    asm volatile("ldmatrix.sync.aligned.m8n8.x4.shared.b16 {%0,%1,%2,%3}, [%4];"
        : "=r"(r[0]), "=r"(r[1]), "=r"(r[2]), "=r"(r[3]) : "r"(addr));
}
__device__ __forceinline__ void ldsm4t(uint32_t* r, uint32_t addr) {
    asm volatile("ldmatrix.sync.aligned.m8n8.x4.trans.shared.b16 {%0,%1,%2,%3}, [%4];"
        : "=r"(r[0]), "=r"(r[1]), "=r"(r[2]), "=r"(r[3]) : "r"(addr));
}
__device__ __forceinline__ void ldsm2(uint32_t* r, uint32_t addr) {
    asm volatile("ldmatrix.sync.aligned.m8n8.x2.shared.b16 {%0,%1}, [%2];"
        : "=r"(r[0]), "=r"(r[1]) : "r"(addr));
}
__device__ __forceinline__ void mma16816(float* d, const uint32_t* a, const uint32_t* b) {
    asm volatile("mma.sync.aligned.m16n8k16.row.col.f32.bf16.bf16.f32 "
        "{%0,%1,%2,%3}, {%4,%5,%6,%7}, {%8,%9}, {%0,%1,%2,%3};"
        : "+f"(d[0]), "+f"(d[1]), "+f"(d[2]), "+f"(d[3])
        : "r"(a[0]), "r"(a[1]), "r"(a[2]), "r"(a[3]), "r"(b[0]), "r"(b[1]));
}
__device__ __forceinline__ void split2(float x, float y, uint32_t& hi, uint32_t& lo) {
    __nv_bfloat162 h = __floats2bfloat162_rn(x, y);
    float2 hf = __bfloat1622float2(h);
    __nv_bfloat162 l = __floats2bfloat162_rn(x - hf.x, y - hf.y);
    hi = *(uint32_t*)&h; lo = *(uint32_t*)&l;
}
#define CP16(dst, src) \
    asm volatile("cp.async.cg.shared.global [%0], [%1], 16;" :: "r"(dst), "l"(src))
#define CP_COMMIT() asm volatile("cp.async.commit_group;" ::: "memory")
#define CP_WAIT1()  asm volatile("cp.async.wait_group 1;" ::: "memory")
#define CP_WAIT0()  asm volatile("cp.async.wait_group 0;" ::: "memory")

// ---------------- repack q/k projections into NT weight layout ----------------
__global__ void repack_kernel(const float* __restrict__ qp, const float* __restrict__ kp,
                              float* __restrict__ W) {
    int idx = blockIdx.x * 256 + threadIdx.x;
    if (idx >= 256*512) return;
    int n = idx >> 9, d = idx & 511;
    int h = n >> 5, o = n & 31;
    W[idx]            = qp[((h<<9)+d)*32 + o];
    W[(256<<9) + idx] = kp[((h<<9)+d)*32 + o];
}

// ---------------- bf16x3 mma.sync GEMM (R4) + optional bf16 hi/lo output ----------------
#define GPAD 40
#define OFF_AH 0
#define OFF_AL 5120
#define OFF_BH 10240
#define OFF_BL 15360
#define GSTG   20480

__global__ __launch_bounds__(256, 1)
void gemm_mma(const float* __restrict__ A, const float* __restrict__ W,
              const float* __restrict__ R, float* __restrict__ C, int mode,
              __nv_bfloat16* __restrict__ Chi, __nv_bfloat16* __restrict__ Clo) {
    extern __shared__ __align__(16) char gsm[];
    __nv_bfloat16* s = (__nv_bfloat16*)gsm;
    uint32_t sb0 = smem_u32(s);

    int tid = threadIdx.x;
    int lane = tid & 31, wid = tid >> 5;
    int wm = wid >> 2, wn = wid & 3;
    int row0 = blockIdx.y * 128, col0 = blockIdx.x * 128;

    float acc[4][4][4];
#pragma unroll
    for (int mi = 0; mi < 4; mi++)
#pragma unroll
        for (int ni = 0; ni < 4; ni++)
#pragma unroll
            for (int e = 0; e < 4; e++) acc[mi][ni][e] = 0.f;

    float4 la[4], lb[4];
    int lrow[4], lc4[4];
#pragma unroll
    for (int it = 0; it < 4; it++) {
        int slot = it * 256 + tid;
        lrow[it] = slot >> 3;
        lc4[it]  = (slot & 7) << 2;
    }

#pragma unroll
    for (int it = 0; it < 4; it++) {
        la[it] = *(const float4*)&A[(size_t)(row0 + lrow[it]) * 512 + lc4[it]];
        lb[it] = *(const float4*)&W[(size_t)(col0 + lrow[it]) * 512 + lc4[it]];
    }
#pragma unroll
    for (int it = 0; it < 4; it++) {
        int base = lrow[it] * GPAD + lc4[it];
        uint2 h, l;
        split2(la[it].x, la[it].y, h.x, l.x); split2(la[it].z, la[it].w, h.y, l.y);
        *(uint2*)&s[OFF_AH + base] = h; *(uint2*)&s[OFF_AL + base] = l;
        split2(lb[it].x, lb[it].y, h.x, l.x); split2(lb[it].z, lb[it].w, h.y, l.y);
        *(uint2*)&s[OFF_BH + base] = h; *(uint2*)&s[OFF_BL + base] = l;
    }
    __syncthreads();

    for (int k = 0; k < 16; k++) {
        int cur = k & 1;
        if (k < 15) {
            int kc = (k + 1) * 32;
#pragma unroll
            for (int it = 0; it < 4; it++) {
                la[it] = *(const float4*)&A[(size_t)(row0 + lrow[it]) * 512 + kc + lc4[it]];
                lb[it] = *(const float4*)&W[(size_t)(col0 + lrow[it]) * 512 + kc + lc4[it]];
            }
        }
        uint32_t sb = sb0 + (uint32_t)cur * (GSTG * 2);
        int l16 = lane & 15;
        uint32_t arow = (uint32_t)(wm * 64 + (lane & 15)) * GPAD + (uint32_t)((lane >> 4) << 3);
        uint32_t brow = (uint32_t)(wn * 32 + (l16 & 7)) * GPAD + (uint32_t)((l16 >> 3) << 3);
#pragma unroll
        for (int ks = 0; ks < 2; ks++) {
            uint32_t a[4][4], bh[4][2], bl[4][2];
#pragma unroll
            for (int mi = 0; mi < 4; mi++)
                ldsm4(a[mi], sb + 2 * (OFF_AH + arow + (uint32_t)(mi * 16) * GPAD + ks * 16));
#pragma unroll
            for (int ni = 0; ni < 4; ni++) {
                uint32_t ba = sb + 2 * (brow + (uint32_t)(ni * 8) * GPAD + ks * 16);
                ldsm2(bh[ni], ba + 2 * OFF_BH);
                ldsm2(bl[ni], ba + 2 * OFF_BL);
            }
#pragma unroll
            for (int mi = 0; mi < 4; mi++)
#pragma unroll
                for (int ni = 0; ni < 4; ni++) mma16816(acc[mi][ni], a[mi], bh[ni]);
#pragma unroll
            for (int mi = 0; mi < 4; mi++)
#pragma unroll
                for (int ni = 0; ni < 4; ni++) mma16816(acc[mi][ni], a[mi], bl[ni]);
#pragma unroll
            for (int mi = 0; mi < 4; mi++)
                ldsm4(a[mi], sb + 2 * (OFF_AL + arow + (uint32_t)(mi * 16) * GPAD + ks * 16));
#pragma unroll
            for (int mi = 0; mi < 4; mi++)
#pragma unroll
                for (int ni = 0; ni < 4; ni++) mma16816(acc[mi][ni], a[mi], bh[ni]);
        }
        if (k < 15) {
            __nv_bfloat16* sn = s + (size_t)((k + 1) & 1) * GSTG;
#pragma unroll
            for (int it = 0; it < 4; it++) {
                int base = lrow[it] * GPAD + lc4[it];
                uint2 h, l;
                split2(la[it].x, la[it].y, h.x, l.x); split2(la[it].z, la[it].w, h.y, l.y);
                *(uint2*)&sn[OFF_AH + base] = h; *(uint2*)&sn[OFF_AL + base] = l;
                split2(lb[it].x, lb[it].y, h.x, l.x); split2(lb[it].z, lb[it].w, h.y, l.y);
                *(uint2*)&sn[OFF_BH + base] = h; *(uint2*)&sn[OFF_BL + base] = l;
            }
        }
        __syncthreads();
    }

    int gid = lane >> 2, tig = lane & 3;
#pragma unroll
    for (int mi = 0; mi < 4; mi++) {
#pragma unroll
        for (int ni = 0; ni < 4; ni++) {
            int rg = row0 + wm * 64 + mi * 16 + gid;
            int cg = col0 + wn * 32 + ni * 8 + tig * 2;
#pragma unroll
            for (int half = 0; half < 2; half++) {
                int r = rg + half * 8;
                float vx = acc[mi][ni][half * 2], vy = acc[mi][ni][half * 2 + 1];
                size_t gi = (size_t)r * 512 + cg;
                if (mode == 1) {
                    float2 rv = *(const float2*)&R[gi];
                    vx += rv.x; vy += rv.y;
                } else if (mode == 2) {
                    float2 rv = *(const float2*)&R[gi];
                    vx = rv.x + vx / (1.f + __expf(-vx));
                    vy = rv.y + vy / (1.f + __expf(-vy));
                }
                float2 ov; ov.x = vx; ov.y = vy;
                *(float2*)&C[gi] = ov;
                if (Chi) {
                    uint32_t hh, ll;
                    split2(vx, vy, hh, ll);
                    *(uint32_t*)&Chi[gi] = hh;
                    *(uint32_t*)&Clo[gi] = ll;
                }
            }
        }
    }
}

// ---------------- RoPE + gain (+ scale folded into q), bf16 hi/lo outputs ----------------
__global__ void rope_kernel(const float* __restrict__ QK, const float* __restrict__ gain,
                            __nv_bfloat16* __restrict__ Qh, __nv_bfloat16* __restrict__ Ql,
                            __nv_bfloat16* __restrict__ Kh, __nv_bfloat16* __restrict__ Kl) {
    int bt = blockIdx.x;
    int t  = bt & (TT - 1);
    int b  = bt >> 11;
    int tid = threadIdx.x;
    int h = tid >> 4, i = tid & 15;
    float freq = powf(10000.f, -(float)i * (1.f / 16.f));
    float ang  = (float)t * freq;
    float c = cosf(ang), s = sinf(ang);
    const float* rowq = QK + (size_t)bt * 512 + h * 32;
    const float* rowk = rowq + 256;
    float g  = gain[h] * 0.17677669529663687f;
    float q1 = rowq[i], q2 = rowq[i + 16];
    float k1 = rowk[i], k2 = rowk[i + 16];
    float qa = (q1 * c - q2 * s) * g;
    float qb = (q2 * c + q1 * s) * g;
    float ka = (k1 * c - k2 * s);
    float kb = (k2 * c + k1 * s);
    size_t base = ((size_t)(b * HH + h) * TT + t) * DP;
    __nv_bfloat16 hh;
    hh = __float2bfloat16_rn(qa); Qh[base + i]      = hh; Ql[base + i]      = __float2bfloat16_rn(qa - __bfloat162float(hh));
    hh = __float2bfloat16_rn(qb); Qh[base + i + 16] = hh; Ql[base + i + 16] = __float2bfloat16_rn(qb - __bfloat162float(hh));
    hh = __float2bfloat16_rn(ka); Kh[base + i]      = hh; Kl[base + i]      = __float2bfloat16_rn(ka - __bfloat162float(hh));
    hh = __float2bfloat16_rn(kb); Kh[base + i + 16] = hh; Kl[base + i + 16] = __float2bfloat16_rn(kb - __bfloat162float(hh));
}

// ---------------- flash attention v2: pre-split bf16 + cp.async pipeline ----------------
// smem per stage (bf16 elems): Kh[64][40]@0, Kl@2560, Vh[64][72]@5120, Vl@9728 -> 14336
// 2 stages = 57344 B. Q staged once in stage 0 region before pipeline.
#define FKP 40
#define FVP 72
#define SKH 0
#define SKL 2560
#define SVH 5120
#define SVL 9728
#define FSTG 14336

__global__ __launch_bounds__(256, 1)
void flash_mma(const __nv_bfloat16* __restrict__ Qh, const __nv_bfloat16* __restrict__ Ql,
               const __nv_bfloat16* __restrict__ Kh, const __nv_bfloat16* __restrict__ Kl,
               const __nv_bfloat16* __restrict__ Vh, const __nv_bfloat16* __restrict__ Vl,
               const float* __restrict__ V, float* __restrict__ Y) {
    extern __shared__ __align__(16) __nv_bfloat16 fs[];
    uint32_t sb = smem_u32(fs);

    int b = blockIdx.z, h = blockIdx.y;
    int qt = (int)gridDim.x - 1 - (int)blockIdx.x;     // heavy blocks first
    int tid = threadIdx.x, lane = tid & 31, wid = tid >> 5;
    int gid = lane >> 2, tig = lane & 3;
    int qrow0 = qt * 128;

    size_t bh = (size_t)(b * HH + h) * TT;
    const __nv_bfloat16* Khg = Kh + bh * DP;
    const __nv_bfloat16* Klg = Kl + bh * DP;
    const __nv_bfloat16* Vhg = Vh + (size_t)b * TT * CC + h * DH;
    const __nv_bfloat16* Vlg = Vl + (size_t)b * TT * CC + h * DH;
    const float* Vb = V + (size_t)b * TT * CC + h * DH;

    // ---- stage Q (pre-split bf16) into stage-0 smem, grab fragments ----
#pragma unroll
    for (int it = 0; it < 4; it++) {
        int c = it * 256 + tid;                  // 1024 chunks of 8 elems
        int row = (c & 511) >> 2, col = (c & 3) << 3;
        const __nv_bfloat16* src = (c < 512) ? (Qh + (bh + qrow0 + row) * DP + col)
                                             : (Ql + (bh + qrow0 + row) * DP + col);
        uint32_t doff = (c < 512) ? (uint32_t)(row * FKP + col) : (uint32_t)(5120 + row * FKP + col);
        *(uint4*)&fs[doff] = *(const uint4*)src;
    }
    __syncthreads();
    uint32_t qfh[2][4], qfl[2][4];
    {
        uint32_t arow = (uint32_t)(wid * 16 + (lane & 15)) * FKP + (uint32_t)((lane >> 4) << 3);
#pragma unroll
        for (int ks = 0; ks < 2; ks++) {
            ldsm4(qfh[ks], sb + 2 * (arow + ks * 16));
            ldsm4(qfl[ks], sb + 2 * (5120 + arow + ks * 16));
        }
    }
    __syncthreads();

    float m0 = -1e30f, m1 = -1e30f, l0 = 0.f, l1 = 0.f;
    float o[8][4];
#pragma unroll
    for (int nt = 0; nt < 8; nt++)
#pragma unroll
        for (int e = 0; e < 4; e++) o[nt][e] = 0.f;

    int wmax = qrow0 + wid * 16 + 15;
    int ntiles = 2 * qt + 2;

    // ---- issue loads for a tile into stage s ----
    auto issue = [&](int t, int s) {
        uint32_t st = sb + 2 * (uint32_t)(s * FSTG);
        int j0 = t * 64;
#pragma unroll
        for (int it = 0; it < 6; it++) {
            int c = it * 256 + tid;              // 1536 chunks of 16B
            if (c < 512) {
                int row = (c & 255) >> 2, col = (c & 3) << 3;
                const __nv_bfloat16* src = (c < 256) ? (Khg + (size_t)(j0 + row) * DP + col)
                                                     : (Klg + (size_t)(j0 + row) * DP + col);
                uint32_t doff = (c < 256) ? (uint32_t)(SKH + row * FKP + col)
                                          : (uint32_t)(SKL + row * FKP + col);
                CP16(st + 2 * doff, src);
            } else {
                int cc = c - 512;
                int row = (cc & 511) >> 3, col = (cc & 7) << 3;
                const __nv_bfloat16* src = (cc < 512) ? (Vhg + (size_t)(j0 + row) * CC + col)
                                                      : (Vlg + (size_t)(j0 + row) * CC + col);
                uint32_t doff = (cc < 512) ? (uint32_t)(SVH + row * FVP + col)
                                           : (uint32_t)(SVL + row * FVP + col);
                CP16(st + 2 * doff, src);
            }
        }
    };

    issue(0, 0);
    CP_COMMIT();

    for (int t = 0; t < ntiles; t++) {
        int s = t & 1;
        if (t + 1 < ntiles) { issue(t + 1, s ^ 1); CP_COMMIT(); CP_WAIT1(); }
        else                { CP_WAIT0(); }
        __syncthreads();

        int j0 = t * 64;
        uint32_t stg = sb + 2 * (uint32_t)(s * FSTG);
        if (j0 <= wmax) {
            // ---- QK^T ----
            float sc[8][4];
#pragma unroll
            for (int nt = 0; nt < 8; nt++)
#pragma unroll
                for (int e = 0; e < 4; e++) sc[nt][e] = 0.f;
            uint32_t kbase = (uint32_t)(lane & 7) * FKP + (uint32_t)(((lane >> 3) & 3) << 3);
#pragma unroll
            for (int nt = 0; nt < 8; nt++) {
                uint32_t kbh[4], kbl[4];
                uint32_t ka = stg + 2 * (kbase + (uint32_t)(nt * 8) * FKP);
                ldsm4(kbh, ka + 2 * SKH);
                ldsm4(kbl, ka + 2 * SKL);
                mma16816(sc[nt], qfh[0], kbh);
                mma16816(sc[nt], qfh[1], kbh + 2);
                mma16816(sc[nt], qfh[0], kbl);
                mma16816(sc[nt], qfh[1], kbl + 2);
                mma16816(sc[nt], qfl[0], kbh);
                mma16816(sc[nt], qfl[1], kbh + 2);
            }
            // ---- causal mask ----
            if (j0 + 63 > qrow0 + wid * 16) {
                int r0 = qrow0 + wid * 16 + gid, r1 = r0 + 8;
#pragma unroll
                for (int nt = 0; nt < 8; nt++) {
                    int c = j0 + nt * 8 + tig * 2;
                    if (c > r0)     sc[nt][0] = -1e30f;
                    if (c + 1 > r0) sc[nt][1] = -1e30f;
                    if (c > r1)     sc[nt][2] = -1e30f;
                    if (c + 1 > r1) sc[nt][3] = -1e30f;
                }
            }
            // ---- online softmax ----
            float mx0 = -1e30f, mx1 = -1e30f;
#pragma unroll
            for (int nt = 0; nt < 8; nt++) {
                mx0 = fmaxf(mx0, fmaxf(sc[nt][0], sc[nt][1]));
                mx1 = fmaxf(mx1, fmaxf(sc[nt][2], sc[nt][3]));
            }
            mx0 = fmaxf(mx0, __shfl_xor_sync(~0u, mx0, 1));
            mx0 = fmaxf(mx0, __shfl_xor_sync(~0u, mx0, 2));
            mx1 = fmaxf(mx1, __shfl_xor_sync(~0u, mx1, 1));
            mx1 = fmaxf(mx1, __shfl_xor_sync(~0u, mx1, 2));
            float mn0 = fmaxf(m0, mx0), mn1 = fmaxf(m1, mx1);
            float cr0 = __expf(m0 - mn0), cr1 = __expf(m1 - mn1);
            m0 = mn0; m1 = mn1;
            float ls0 = 0.f, ls1 = 0.f;
#pragma unroll
            for (int nt = 0; nt < 8; nt++) {
                sc[nt][0] = __expf(sc[nt][0] - m0);
                sc[nt][1] = __expf(sc[nt][1] - m0);
                sc[nt][2] = __expf(sc[nt][2] - m1);
                sc[nt][3] = __expf(sc[nt][3] - m1);
                ls0 += sc[nt][0] + sc[nt][1];
                ls1 += sc[nt][2] + sc[nt][3];
            }
            l0 = l0 * cr0 + ls0;
            l1 = l1 * cr1 + ls1;
#pragma unroll
            for (int nt = 0; nt < 8; nt++) {
                o[nt][0] *= cr0; o[nt][1] *= cr0;
                o[nt][2] *= cr1; o[nt][3] *= cr1;
            }
            // ---- P @ V ----
            uint32_t vbase = (uint32_t)(lane & 15) * FVP + (uint32_t)((lane >> 4) << 3);
#pragma unroll
            for (int kk = 0; kk < 4; kk++) {
                uint32_t ah[4], al[4];
                split2(sc[2*kk][0],   sc[2*kk][1],   ah[0], al[0]);
                split2(sc[2*kk][2],   sc[2*kk][3],   ah[1], al[1]);
                split2(sc[2*kk+1][0], sc[2*kk+1][1], ah[2], al[2]);
                split2(sc[2*kk+1][2], sc[2*kk+1][3], ah[3], al[3]);
#pragma unroll
                for (int nv = 0; nv < 4; nv++) {
                    uint32_t vbh[4], vbl[4];
                    uint32_t va = stg + 2 * (vbase + (uint32_t)(kk * 16) * FVP + (uint32_t)(nv * 16));
                    ldsm4t(vbh, va + 2 * SVH);
                    ldsm4t(vbl, va + 2 * SVL);
                    mma16816(o[2*nv],     ah, vbh);
                    mma16816(o[2*nv + 1], ah, vbh + 2);
                    mma16816(o[2*nv],     ah, vbl);
                    mma16816(o[2*nv + 1], ah, vbl + 2);
                    mma16816(o[2*nv],     al, vbh);
                    mma16816(o[2*nv + 1], al, vbh + 2);
                }
            }
        }
        __syncthreads();
    }

    // ---- finalize ----
    l0 += __shfl_xor_sync(~0u, l0, 1); l0 += __shfl_xor_sync(~0u, l0, 2);
    l1 += __shfl_xor_sync(~0u, l1, 1); l1 += __shfl_xor_sync(~0u, l1, 2);
    float inv0 = 1.f / l0, inv1 = 1.f / l1;
#pragma unroll
    for (int nt = 0; nt < 8; nt++) {
        o[nt][0] *= inv0; o[nt][1] *= inv0;
        o[nt][2] *= inv1; o[nt][3] *= inv1;
    }
    int i0 = qrow0 + wid * 16 + gid, i1 = i0 + 8;
    float dot0 = 0.f, n20 = 0.f, dot1 = 0.f, n21 = 0.f;
#pragma unroll
    for (int nt = 0; nt < 8; nt++) {
        int d = nt * 8 + tig * 2;
        float2 v0 = *(const float2*)&Vb[(size_t)i0 * CC + d];
        float2 v1 = *(const float2*)&Vb[(size_t)i1 * CC + d];
        dot0 += o[nt][0] * v0.x + o[nt][1] * v0.y;
        n20  += v0.x * v0.x + v0.y * v0.y;
        dot1 += o[nt][2] * v1.x + o[nt][3] * v1.y;
        n21  += v1.x * v1.x + v1.y * v1.y;
    }
    dot0 += __shfl_xor_sync(~0u, dot0, 1); dot0 += __shfl_xor_sync(~0u, dot0, 2);
    n20  += __shfl_xor_sync(~0u, n20, 1);  n20  += __shfl_xor_sync(~0u, n20, 2);
    dot1 += __shfl_xor_sync(~0u, dot1, 1); dot1 += __shfl_xor_sync(~0u, dot1, 2);
    n21  += __shfl_xor_sync(~0u, n21, 1);  n21  += __shfl_xor_sync(~0u, n21, 2);
    float nr0 = fmaxf(sqrtf(n20), 1e-12f);
    float nr1 = fmaxf(sqrtf(n21), 1e-12f);
    dot0 /= (nr0 * nr0);
    dot1 /= (nr1 * nr1);
    float* Y0 = Y + (size_t)(b * TT + i0) * CC + h * DH;
    float* Y1 = Y + (size_t)(b * TT + i1) * CC + h * DH;
#pragma unroll
    for (int nt = 0; nt < 8; nt++) {
        int d = nt * 8 + tig * 2;
        float2 v0 = *(const float2*)&Vb[(size_t)i0 * CC + d];
        float2 v1 = *(const float2*)&Vb[(size_t)i1 * CC + d];
        float2 y0, y1;
        y0.x = o[nt][0] - dot0 * v0.x; y0.y = o[nt][1] - dot0 * v0.y;
        y1.x = o[nt][2] - dot1 * v1.x; y1.y = o[nt][3] - dot1 * v1.y;
        *(float2*)&Y0[d] = y0;
        *(float2*)&Y1[d] = y1;
    }
}

// ---------------- layernorm (row of 512) ----------------
__global__ void ln_kernel(const float* __restrict__ X, const float* __restrict__ g,
                          const float* __restrict__ bta, float* __restrict__ O) {
    int row = blockIdx.x;
    int t = threadIdx.x;
    __shared__ float red[4], red2[4];
    const float* xp = X + (size_t)row * 512;
    float4 v = *(const float4*)&xp[t * 4];
    float s = v.x + v.y + v.z + v.w;
#pragma unroll
    for (int off = 16; off; off >>= 1) s += __shfl_xor_sync(~0u, s, off);
    if ((t & 31) == 0) red[t >> 5] = s;
    __syncthreads();
    float mean = (red[0] + red[1] + red[2] + red[3]) * (1.f / 512.f);
    float dx = v.x - mean, dy = v.y - mean, dz = v.z - mean, dw = v.w - mean;
    float s2 = dx*dx + dy*dy + dz*dz + dw*dw;
#pragma unroll
    for (int off = 16; off; off >>= 1) s2 += __shfl_xor_sync(~0u, s2, off);
    if ((t & 31) == 0) red2[t >> 5] = s2;
    __syncthreads();
    float var = (red2[0] + red2[1] + red2[2] + red2[3]) * (1.f / 512.f);
    float rsv = rsqrtf(var + 1e-5f);
    float4 gg = *(const float4*)&g[t * 4];
    float4 bb = *(const float4*)&bta[t * 4];
    float4 ov;
    ov.x = dx * rsv * gg.x + bb.x;
    ov.y = dy * rsv * gg.y + bb.y;
    ov.z = dz * rsv * gg.z + bb.z;
    ov.w = dw * rsv * gg.w + bb.w;
    *(float4*)&O[(size_t)row * 512 + t * 4] = ov;
}

// ---------------- rms + out-proj (32) + tanh/temp ----------------
__global__ void final_kernel(const float* __restrict__ X, const float* __restrict__ Wout,
                             const float* __restrict__ ct, float* __restrict__ Z) {
    int row = blockIdx.x;
    int t = threadIdx.x;
    __shared__ __align__(16) float xs[512];
    __shared__ float red[8];
    __shared__ float pm[32][9];
    const float* xp = X + (size_t)row * 512;
    float2 v = *(const float2*)&xp[t * 2];
    float s2 = v.x * v.x + v.y * v.y;
#pragma unroll
    for (int off = 16; off; off >>= 1) s2 += __shfl_xor_sync(~0u, s2, off);
    if ((t & 31) == 0) red[t >> 5] = s2;
    __syncthreads();
    float tot = 0.f;
#pragma unroll
    for (int w = 0; w < 8; w++) tot += red[w];
    float rs = rsqrtf(tot * (1.f / 512.f) + 1e-6f);
    xs[t*2] = v.x * rs; xs[t*2+1] = v.y * rs;
    __syncthreads();
    int mi = t >> 3, seg = t & 7;
    const float* wrow = Wout + mi * 512 + seg * 64;
    const float* xseg = xs + seg * 64;
    float acc = 0.f;
#pragma unroll
    for (int d = 0; d < 64; d += 4) {
        float4 wv = *(const float4*)&wrow[d];
        acc += xseg[d]*wv.x + xseg[d+1]*wv.y + xseg[d+2]*wv.z + xseg[d+3]*wv.w;
    }
    pm[mi][seg] = acc;
    __syncthreads();
    if (t < 32) {
        float a = 0.f;
#pragma unroll
        for (int sgi = 0; sgi < 8; sgi++) a += pm[t][sgi];
        float cv = ct[t];
        float sp = (cv > 20.f) ? cv : log1pf(expf(cv));
        Z[(size_t)row * 32 + t] = tanhf(a / (sp + 1e-4f));
    }
}

// ---------------- launch ----------------
extern "C" void kernel_launch(void* const* d_in, const int* in_sizes, int n_in,
                              void* d_out, int out_size) {
    const float* x       = (const float*)d_in[0];
    const float* q_projs = (const float*)d_in[1];
    const float* k_projs = (const float*)d_in[2];
    const float* w_v     = (const float*)d_in[3];
    const float* w_proj  = (const float*)d_in[4];
    const float* q_gain  = (const float*)d_in[5];
    const float* enc_w0  = (const float*)d_in[6];
    const float* ln1g    = (const float*)d_in[7];
    const float* ln1b    = (const float*)d_in[8];
    const float* enc_w1  = (const float*)d_in[9];
    const float* ln2g    = (const float*)d_in[10];
    const float* ln2b    = (const float*)d_in[11];
    const float* enc_w2  = (const float*)d_in[12];
    const float* enc_wo  = (const float*)d_in[13];
    const float* ctemp   = (const float*)d_in[14];
    float* out = (float*)d_out;

    float *p_wqk, *p_qk, *p_v, *p_y, *p_h, *p_t0, *p_ln, *p_t1, *p_t2;
    __nv_bfloat16 *p_qh, *p_ql, *p_kh, *p_kl, *p_vh, *p_vl;
    cudaGetSymbolAddress((void**)&p_wqk, g_wqk);
    cudaGetSymbolAddress((void**)&p_qk,  g_qk);
    cudaGetSymbolAddress((void**)&p_v,   g_v);
    cudaGetSymbolAddress((void**)&p_y,   g_y);
    cudaGetSymbolAddress((void**)&p_h,   g_h);
    cudaGetSymbolAddress((void**)&p_t0,  g_t0);
    cudaGetSymbolAddress((void**)&p_ln,  g_ln);
    cudaGetSymbolAddress((void**)&p_t1,  g_t1);
    cudaGetSymbolAddress((void**)&p_t2,  g_t2);
    cudaGetSymbolAddress((void**)&p_qh,  g_qh);
    cudaGetSymbolAddress((void**)&p_ql,  g_ql);
    cudaGetSymbolAddress((void**)&p_kh,  g_kh);
    cudaGetSymbolAddress((void**)&p_kl,  g_kl);
    cudaGetSymbolAddress((void**)&p_vh,  g_vh);
    cudaGetSymbolAddress((void**)&p_vl,  g_vl);

    const int GEMM_SMEM  = 2 * GSTG * 2;   // 81920 B
    const int FLASH_SMEM = 2 * FSTG * 2;   // 57344 B
    cudaFuncSetAttribute(gemm_mma,  cudaFuncAttributeMaxDynamicSharedMemorySize, GEMM_SMEM);
    cudaFuncSetAttribute(flash_mma, cudaFuncAttributeMaxDynamicSharedMemorySize, FLASH_SMEM);

    dim3 ggrid(512 / 128, MM / 128);   // (4, 32)

    repack_kernel<<<512, 256>>>(q_projs, k_projs, p_wqk);
    gemm_mma<<<ggrid, 256, GEMM_SMEM>>>(x, p_wqk, nullptr, p_qk, 0, nullptr, nullptr);
    rope_kernel<<<MM, 128>>>(p_qk, q_gain, p_qh, p_ql, p_kh, p_kl);
    gemm_mma<<<ggrid, 256, GEMM_SMEM>>>(x, w_v, nullptr, p_v, 0, p_vh, p_vl);
    flash_mma<<<dim3(TT / 128, HH, BB), 256, FLASH_SMEM>>>(p_qh, p_ql, p_kh, p_kl,
                                                           p_vh, p_vl, p_v, p_y);
    gemm_mma<<<ggrid, 256, GEMM_SMEM>>>(p_y, w_proj, x, p_h, 1, nullptr, nullptr);
    gemm_mma<<<ggrid, 256, GEMM_SMEM>>>(p_h, enc_w0, nullptr, p_t0, 0, nullptr, nullptr);
    ln_kernel<<<MM, 128>>>(p_t0, ln1g, ln1b, p_ln);
    gemm_mma<<<ggrid, 256, GEMM_SMEM>>>(p_ln, enc_w1, p_h, p_t1, 2, nullptr, nullptr);
    ln_kernel<<<MM, 128>>>(p_t1, ln2g, ln2b, p_ln);
    gemm_mma<<<ggrid, 256, GEMM_SMEM>>>(p_ln, enc_w2, p_t1, p_t2, 2, nullptr, nullptr);
    final_kernel<<<MM, 256>>>(p_t2, enc_wo, ctemp, out);
}